// round 3
// baseline (speedup 1.0000x reference)
#include <cuda_runtime.h>

#define NN   8192
#define F    768
#define HIDD 384
#define OUTD 10
#define NNZ  (NN * 16)
#define DCAT (F + 2 * HIDD)

#define BM 128
#define BN 128
#define BK 8

// ---------------- scratch (device globals; no allocation allowed) ----------------
__device__ float    g_xn[NN * F];
__device__ float    g_xt[NN * F];
__device__ float    g_et[NN * F];
__device__ float    g_efeat[NN * F];
__device__ float    g_h[NN * F];
__device__ float    g_out1[NN * HIDD];
__device__ float    g_out2[NN * HIDD];
__device__ float    g_catT[(size_t)DCAT * NN];
__device__ float    g_alpha[NNZ];
__device__ float    g_ax[NN];
__device__ float    g_ae[NN];
__device__ unsigned g_segmax[NN];
__device__ float    g_segsum[NN];
__device__ float    g_dege[NN];
__device__ float    g_degn[NN];
__device__ float    g_colsum[F];
__device__ float    g_colsq[F];
__device__ float    g_score[DCAT];
__device__ float    g_wp[OUTD * DCAT];

// ---------------- small utility kernels ----------------
__global__ void k_zero_gn() {
    int c = threadIdx.x;
    if (c < F) { g_colsum[c] = 0.f; g_colsq[c] = 0.f; }
}

__global__ void k_zero_score() {
    int d = blockIdx.x * blockDim.x + threadIdx.x;
    if (d < DCAT) g_score[d] = 0.f;
}

// zero per-conv state: efeat, h, seg reductions, degrees
__global__ void k_init_conv() {
    int idx = blockIdx.x * blockDim.x + threadIdx.x;
    if (idx < NN * F) { g_efeat[idx] = 0.f; g_h[idx] = 0.f; }
    if (idx < NN) {
        g_segsum[idx] = 0.f;
        g_segmax[idx] = 0u;   // ordered-key 0 < key of every real float
        g_dege[idx]   = 0.f;
        g_degn[idx]   = 0.f;
    }
}

// ---------------- GraphNorm ----------------
// column sums/squares: grid = NN/64 blocks of 768 threads (1 thread per feature)
__global__ void k_gn_reduce(const float* __restrict__ X) {
    int c  = threadIdx.x;
    int r0 = blockIdx.x * 64;
    float s = 0.f, q = 0.f;
    for (int i = 0; i < 64; i++) {
        float v = X[(size_t)(r0 + i) * F + c];
        s += v;
        q += v * v;
    }
    atomicAdd(&g_colsum[c], s);
    atomicAdd(&g_colsq[c], q);
}

__global__ void k_gn_apply(const float* __restrict__ X,
                           const float* __restrict__ w,
                           const float* __restrict__ b,
                           const float* __restrict__ ms) {
    int idx = blockIdx.x * blockDim.x + threadIdx.x;
    if (idx >= NN * F) return;
    int c = idx % F;
    float invN  = 1.f / (float)NN;
    float mean  = g_colsum[c] * invN;
    float m     = ms[c];
    float var   = g_colsq[c] * invN - m * (2.f - m) * mean * mean;
    float out   = X[idx] - m * mean;
    g_xn[idx]   = w[c] * out * rsqrtf(var + 1e-5f) + b[c];
}

// ---------------- generic NT GEMM: C[M,Nc] = A[M,K] * B[Nc,K]^T ----------------
// mode 0: plain store. mode 1: C = lrelu(acc + bias[col], 0.01).
// mode 2: no C store; score[row] += sum_col relu(acc + bias[col]) * w2[col].
__global__ __launch_bounds__(256, 2) void k_gemm_nt(
    const float* __restrict__ A, const float* __restrict__ B, float* __restrict__ C,
    int M, int Nc, int K, int mode,
    const float* __restrict__ bias, const float* __restrict__ w2,
    float* __restrict__ score)
{
    __shared__ __align__(16) float As[BK][BM];
    __shared__ __align__(16) float Bs[BK][BN];
    __shared__ float red[BM];

    const int tid  = threadIdx.x;
    const int tx   = tid & 15;
    const int ty   = tid >> 4;
    const int row0 = blockIdx.y * BM;
    const int col0 = blockIdx.x * BN;
    const int lr   = tid >> 1;
    const int lk   = (tid & 1) << 2;

    const float* Ag = A + (size_t)(row0 + lr) * K + lk;
    const float* Bg = B + (size_t)(col0 + lr) * K + lk;

    float acc[8][8];
#pragma unroll
    for (int i = 0; i < 8; i++)
#pragma unroll
        for (int j = 0; j < 8; j++) acc[i][j] = 0.f;

    float4 av = *(const float4*)Ag;
    float4 bv = *(const float4*)Bg;

    for (int k0 = 0; k0 < K; k0 += BK) {
        As[lk + 0][lr] = av.x; As[lk + 1][lr] = av.y;
        As[lk + 2][lr] = av.z; As[lk + 3][lr] = av.w;
        Bs[lk + 0][lr] = bv.x; Bs[lk + 1][lr] = bv.y;
        Bs[lk + 2][lr] = bv.z; Bs[lk + 3][lr] = bv.w;
        __syncthreads();
        if (k0 + BK < K) {
            av = *(const float4*)(Ag + k0 + BK);
            bv = *(const float4*)(Bg + k0 + BK);
        }
#pragma unroll
        for (int kk = 0; kk < BK; kk++) {
            float4 a0 = *(const float4*)&As[kk][ty << 3];
            float4 a1 = *(const float4*)&As[kk][(ty << 3) + 4];
            float4 b0 = *(const float4*)&Bs[kk][tx << 3];
            float4 b1 = *(const float4*)&Bs[kk][(tx << 3) + 4];
            float a[8] = {a0.x, a0.y, a0.z, a0.w, a1.x, a1.y, a1.z, a1.w};
            float b[8] = {b0.x, b0.y, b0.z, b0.w, b1.x, b1.y, b1.z, b1.w};
#pragma unroll
            for (int i = 0; i < 8; i++)
#pragma unroll
                for (int j = 0; j < 8; j++)
                    acc[i][j] = fmaf(a[i], b[j], acc[i][j]);
        }
        __syncthreads();
    }

    const int crow = row0 + (ty << 3);
    const int ccol = col0 + (tx << 3);

    if (mode == 2) {
        float part[8];
#pragma unroll
        for (int i = 0; i < 8; i++) part[i] = 0.f;
#pragma unroll
        for (int j = 0; j < 8; j++) {
            float b1v = bias[ccol + j];
            float w2v = w2[ccol + j];
#pragma unroll
            for (int i = 0; i < 8; i++) {
                float p = acc[i][j] + b1v;
                p = p > 0.f ? p : 0.f;
                part[i] = fmaf(p, w2v, part[i]);
            }
        }
        if (tid < BM) red[tid] = 0.f;
        __syncthreads();
#pragma unroll
        for (int i = 0; i < 8; i++) atomicAdd(&red[(ty << 3) + i], part[i]);
        __syncthreads();
        if (tid < BM) atomicAdd(&score[row0 + tid], red[tid]);
        return;
    }

#pragma unroll
    for (int i = 0; i < 8; i++) {
        float* Cp = C + (size_t)(crow + i) * Nc + ccol;
        if (mode == 1) {
            float o[8];
#pragma unroll
            for (int j = 0; j < 8; j++) {
                float v = acc[i][j] + bias[ccol + j];
                o[j] = v >= 0.f ? v : 0.01f * v;
            }
            *(float4*)Cp       = make_float4(o[0], o[1], o[2], o[3]);
            *(float4*)(Cp + 4) = make_float4(o[4], o[5], o[6], o[7]);
        } else {
            *(float4*)Cp       = make_float4(acc[i][0], acc[i][1], acc[i][2], acc[i][3]);
            *(float4*)(Cp + 4) = make_float4(acc[i][4], acc[i][5], acc[i][6], acc[i][7]);
        }
    }
}

// ---------------- attention-coefficient GEMVs: ax = xt@att[:F], ae = et@att[F:] ----------------
__global__ void k_gemv_att(const float* __restrict__ att) {
    int w    = (blockIdx.x * blockDim.x + threadIdx.x) >> 5;
    int lane = threadIdx.x & 31;
    if (w >= NN) return;
    const float* xr = g_xt + (size_t)w * F;
    const float* er = g_et + (size_t)w * F;
    float s1 = 0.f, s2 = 0.f;
    for (int i = lane; i < F; i += 32) {
        s1 = fmaf(xr[i], att[i],     s1);
        s2 = fmaf(er[i], att[F + i], s2);
    }
#pragma unroll
    for (int off = 16; off; off >>= 1) {
        s1 += __shfl_xor_sync(0xffffffffu, s1, off);
        s2 += __shfl_xor_sync(0xffffffffu, s2, off);
    }
    if (lane == 0) { g_ax[w] = s1; g_ae[w] = s2; }
}

// ---------------- edge kernels ----------------
__device__ __forceinline__ unsigned fkey(float f) {
    unsigned k = __float_as_uint(f);
    return (k & 0x80000000u) ? ~k : (k | 0x80000000u);
}
__device__ __forceinline__ float fkey_inv(unsigned k) {
    return (k & 0x80000000u) ? __uint_as_float(k & 0x7FFFFFFFu) : __uint_as_float(~k);
}

__global__ void k_edge1(const int* __restrict__ ei) {
    int e = blockIdx.x * blockDim.x + threadIdx.x;
    if (e >= NNZ) return;
    int r = ei[e], c = ei[NNZ + e];
    float a = g_ax[r] + g_ae[c];
    a = a >= 0.f ? a : 0.2f * a;          // leaky relu 0.2
    g_alpha[e] = a;
    atomicMax(&g_segmax[c], fkey(a));
    atomicAdd(&g_degn[r], 1.f);
    atomicAdd(&g_dege[c], 1.f);
}

__global__ void k_edge2(const int* __restrict__ ei) {
    int e = blockIdx.x * blockDim.x + threadIdx.x;
    if (e >= NNZ) return;
    int c = ei[NNZ + e];
    float m  = fkey_inv(g_segmax[c]);
    float ex = expf(g_alpha[e] - m);
    g_alpha[e] = ex;
    atomicAdd(&g_segsum[c], ex);
}

// node -> hyperedge: efeat[c] += (Bn[c]*alpha) * xt[r]
__global__ void k_edge3(const int* __restrict__ ei) {
    int e = blockIdx.x;
    int r = ei[e], c = ei[NNZ + e];
    float de   = g_dege[c];
    float bn   = de > 0.f ? 1.f / de : 0.f;
    float coef = bn * (g_alpha[e] / (g_segsum[c] + 1e-16f));
    int f4 = threadIdx.x * 4;
    float4 v = *(const float4*)&g_xt[(size_t)r * F + f4];
    float* dst = &g_efeat[(size_t)c * F + f4];
    atomicAdd(dst + 0, coef * v.x);
    atomicAdd(dst + 1, coef * v.y);
    atomicAdd(dst + 2, coef * v.z);
    atomicAdd(dst + 3, coef * v.w);
}

// hyperedge -> node: h[r] += (Dn[r]*alpha) * efeat[c]
__global__ void k_edge4(const int* __restrict__ ei) {
    int e = blockIdx.x;
    int r = ei[e], c = ei[NNZ + e];
    float dn   = g_degn[r];
    float dcoef = dn > 0.f ? 1.f / dn : 0.f;
    float coef = dcoef * (g_alpha[e] / (g_segsum[c] + 1e-16f));
    int f4 = threadIdx.x * 4;
    float4 v = *(const float4*)&g_efeat[(size_t)c * F + f4];
    float* dst = &g_h[(size_t)r * F + f4];
    atomicAdd(dst + 0, coef * v.x);
    atomicAdd(dst + 1, coef * v.y);
    atomicAdd(dst + 2, coef * v.z);
    atomicAdd(dst + 3, coef * v.w);
}

__global__ void k_bias_lrelu(const float* __restrict__ b) {
    int idx = blockIdx.x * blockDim.x + threadIdx.x;
    if (idx >= NN * F) return;
    int c = idx % F;
    float v = g_h[idx] + b[c];
    g_h[idx] = v >= 0.f ? v : 0.01f * v;
}

// ---------------- transpose src[NN,C] into dst so dst[c*NN + r] = src[r*C + c] ----------------
__global__ void k_transpose(const float* __restrict__ src, int C, float* __restrict__ dst) {
    __shared__ float t[32][33];
    int c0 = blockIdx.x * 32, r0 = blockIdx.y * 32;
    int tx = threadIdx.x, ty = threadIdx.y;
#pragma unroll
    for (int i = 0; i < 4; i++)
        t[ty + 8 * i][tx] = src[(size_t)(r0 + ty + 8 * i) * C + c0 + tx];
    __syncthreads();
#pragma unroll
    for (int i = 0; i < 4; i++)
        dst[(size_t)(c0 + ty + 8 * i) * NN + r0 + tx] = t[tx][ty + 8 * i];
}

// ---------------- score finalize + folded classifier ----------------
__global__ void k_score_final(const float* __restrict__ b2, const float* __restrict__ center) {
    int d = blockIdx.x * blockDim.x + threadIdx.x;
    if (d >= DCAT) return;
    float r = g_score[d] + b2[0];
    float sg = 1.f / (1.f + expf(-r));
    g_score[d] = sg - center[d];
}

__global__ void k_wp(const float* __restrict__ clsW) {
    int idx = blockIdx.x * blockDim.x + threadIdx.x;
    if (idx >= OUTD * DCAT) return;
    g_wp[idx] = clsW[idx] * g_score[idx % DCAT];
}

// logits[n, o] = sum_d cat[n,d] * wp[o,d] + cls_b[o]; cat segments read row-major.
__global__ void k_logits(const float* __restrict__ x, const float* __restrict__ clsb,
                         float* __restrict__ out) {
    int n    = (blockIdx.x * blockDim.x + threadIdx.x) >> 5;
    int lane = threadIdx.x & 31;
    if (n >= NN) return;
    float acc[OUTD];
#pragma unroll
    for (int o = 0; o < OUTD; o++) acc[o] = 0.f;

    const float* xr = x + (size_t)n * F;
#pragma unroll
    for (int it = 0; it < 6; it++) {
        int i = lane * 4 + it * 128;
        float4 v = *(const float4*)&xr[i];
#pragma unroll
        for (int o = 0; o < OUTD; o++) {
            float4 w = *(const float4*)&g_wp[o * DCAT + i];
            acc[o] += v.x * w.x + v.y * w.y + v.z * w.z + v.w * w.w;
        }
    }
    const float* o1 = g_out1 + (size_t)n * HIDD;
#pragma unroll
    for (int it = 0; it < 3; it++) {
        int i = lane * 4 + it * 128;
        float4 v = *(const float4*)&o1[i];
#pragma unroll
        for (int o = 0; o < OUTD; o++) {
            float4 w = *(const float4*)&g_wp[o * DCAT + F + i];
            acc[o] += v.x * w.x + v.y * w.y + v.z * w.z + v.w * w.w;
        }
    }
    const float* o2 = g_out2 + (size_t)n * HIDD;
#pragma unroll
    for (int it = 0; it < 3; it++) {
        int i = lane * 4 + it * 128;
        float4 v = *(const float4*)&o2[i];
#pragma unroll
        for (int o = 0; o < OUTD; o++) {
            float4 w = *(const float4*)&g_wp[o * DCAT + F + HIDD + i];
            acc[o] += v.x * w.x + v.y * w.y + v.z * w.z + v.w * w.w;
        }
    }
#pragma unroll
    for (int o = 0; o < OUTD; o++) {
        float v = acc[o];
#pragma unroll
        for (int off = 16; off; off >>= 1) v += __shfl_xor_sync(0xffffffffu, v, off);
        if (lane == 0) out[(size_t)n * OUTD + o] = v + clsb[o];
    }
}

// ---------------- host-side conv driver ----------------
static void run_conv(const float* feat_in, const int* ei, const float* eattr,
                     const float* gw, const float* gb, const float* gms,
                     const float* W, const float* att, const float* hb,
                     float* p_xn, float* p_xt, float* p_et)
{
    k_zero_gn<<<1, 768>>>();
    k_gn_reduce<<<NN / 64, 768>>>(feat_in);
    k_gn_apply<<<NN * F / 256, 256>>>(feat_in, gw, gb, gms);
    k_init_conv<<<NN * F / 256, 256>>>();
    k_gemm_nt<<<dim3(F / BN, NN / BM), 256>>>(p_xn, W, p_xt, NN, F, F, 0, nullptr, nullptr, nullptr);
    k_gemm_nt<<<dim3(F / BN, NN / BM), 256>>>(eattr, W, p_et, NN, F, F, 0, nullptr, nullptr, nullptr);
    k_gemv_att<<<NN / 8, 256>>>(att);
    k_edge1<<<NNZ / 256, 256>>>(ei);
    k_edge2<<<NNZ / 256, 256>>>(ei);
    k_edge3<<<NNZ, 192>>>(ei);
    k_edge4<<<NNZ, 192>>>(ei);
    k_bias_lrelu<<<NN * F / 256, 256>>>(hb);
}

extern "C" void kernel_launch(void* const* d_in, const int* in_sizes, int n_in,
                              void* d_out, int out_size) {
    const float* x       = (const float*)d_in[0];
    const int*   ei      = (const int*)  d_in[1];
    const float* eattr   = (const float*)d_in[2];
    const float* gn1_w   = (const float*)d_in[3];
    const float* gn1_b   = (const float*)d_in[4];
    const float* gn1_ms  = (const float*)d_in[5];
    const float* gn2_w   = (const float*)d_in[6];
    const float* gn2_b   = (const float*)d_in[7];
    const float* gn2_ms  = (const float*)d_in[8];
    const float* hg1_W   = (const float*)d_in[9];
    const float* hg1_att = (const float*)d_in[10];
    const float* hg1_b   = (const float*)d_in[11];
    const float* hg2_W   = (const float*)d_in[12];
    const float* hg2_att = (const float*)d_in[13];
    const float* hg2_b   = (const float*)d_in[14];
    const float* fc1_W   = (const float*)d_in[15];
    const float* fc1_b   = (const float*)d_in[16];
    const float* fc2_W   = (const float*)d_in[17];
    const float* fc2_b   = (const float*)d_in[18];
    const float* attn_W1 = (const float*)d_in[19];
    const float* attn_b1 = (const float*)d_in[20];
    const float* attn_W2 = (const float*)d_in[21];
    const float* attn_b2 = (const float*)d_in[22];
    const float* cls_W   = (const float*)d_in[23];
    const float* cls_b   = (const float*)d_in[24];
    const float* center  = (const float*)d_in[25];
    float*       out     = (float*)d_out;

    float *p_xn, *p_xt, *p_et, *p_h, *p_out1, *p_out2, *p_catT, *p_score;
    cudaGetSymbolAddress((void**)&p_xn,    g_xn);
    cudaGetSymbolAddress((void**)&p_xt,    g_xt);
    cudaGetSymbolAddress((void**)&p_et,    g_et);
    cudaGetSymbolAddress((void**)&p_h,     g_h);
    cudaGetSymbolAddress((void**)&p_out1,  g_out1);
    cudaGetSymbolAddress((void**)&p_out2,  g_out2);
    cudaGetSymbolAddress((void**)&p_catT,  g_catT);
    cudaGetSymbolAddress((void**)&p_score, g_score);

    // ---- conv1 + fc1 ----
    run_conv(x, ei, eattr, gn1_w, gn1_b, gn1_ms, hg1_W, hg1_att, hg1_b, p_xn, p_xt, p_et);
    k_gemm_nt<<<dim3(HIDD / BN, NN / BM), 256>>>(p_h, fc1_W, p_out1, NN, HIDD, F, 1, fc1_b, nullptr, nullptr);

    // ---- conv2 (reads g_h = h1 for graphnorm BEFORE re-zeroing) + fc2 ----
    run_conv(p_h, ei, eattr, gn2_w, gn2_b, gn2_ms, hg2_W, hg2_att, hg2_b, p_xn, p_xt, p_et);
    k_gemm_nt<<<dim3(HIDD / BN, NN / BM), 256>>>(p_h, fc2_W, p_out2, NN, HIDD, F, 1, fc2_b, nullptr, nullptr);

    // ---- assemble catT = [x; out1; out2]^T (feature-major, node-contiguous) ----
    k_transpose<<<dim3(F / 32,    NN / 32), dim3(32, 8)>>>(x,      F,    p_catT);
    k_transpose<<<dim3(HIDD / 32, NN / 32), dim3(32, 8)>>>(p_out1, HIDD, p_catT + (size_t)F * NN);
    k_transpose<<<dim3(HIDD / 32, NN / 32), dim3(32, 8)>>>(p_out2, HIDD, p_catT + (size_t)(F + HIDD) * NN);

    // ---- attention: score[d] = sum_j relu(catT@W1^T + b1)[d,j] * W2[j], fused epilogue ----
    k_zero_score<<<(DCAT + 255) / 256, 256>>>();
    k_gemm_nt<<<dim3(NN / BN, DCAT / BM), 256>>>(p_catT, attn_W1, nullptr, DCAT, NN, NN, 2,
                                                 attn_b1, attn_W2, p_score);
    k_score_final<<<(DCAT + 255) / 256, 256>>>(attn_b2, center);

    // ---- classifier with score folded into weights ----
    k_wp<<<(OUTD * DCAT + 255) / 256, 256>>>(cls_W);
    k_logits<<<NN * 32 / 256, 256>>>(x, cls_b, out);
}

// round 5
// speedup vs baseline: 2.5422x; 2.5422x over previous
#include <cuda_runtime.h>
#include <cstdint>

#define NN   8192
#define F    768
#define HIDD 384
#define OUTD 10
#define NNZ  (NN * 16)
#define DCAT (F + 2 * HIDD)

#define KC      32                 // fp32 per K-chunk (128 B per smem row)
#define STAGES  3
#define ABYTES  (128 * 128)        // 128 rows x 128 B
#define STAGE_BYTES (2 * ABYTES)   // A tile + B tile
#define SMEM_GEMM (STAGES * STAGE_BYTES + 1024)

// ---------------- scratch (device globals; no allocation allowed) ----------------
__device__ float    g_xn[NN * F];
__device__ float    g_xt[NN * F];
__device__ float    g_et[NN * F];
__device__ float    g_efeat[NN * F];
__device__ float    g_h[NN * F];
__device__ float    g_out1[NN * HIDD];
__device__ float    g_out2[NN * HIDD];
__device__ float    g_catT[(size_t)DCAT * NN];
__device__ float    g_alpha[NNZ];
__device__ float    g_ax[NN];
__device__ float    g_ae[NN];
__device__ unsigned g_segmax[NN];
__device__ float    g_segsum[NN];
__device__ float    g_dege[NN];
__device__ float    g_degn[NN];
__device__ float    g_colsum[F];
__device__ float    g_colsq[F];
__device__ float    g_score[DCAT];
__device__ float    g_wp[OUTD * DCAT];

// ---------------- PTX helpers (plain sm_103-safe: sm_80+ features only) ----------------
__device__ __forceinline__ uint32_t smem_u32(const void* p) {
    uint32_t a;
    asm("{ .reg .u64 t; cvta.to.shared.u64 t, %1; cvt.u32.u64 %0, t; }" : "=r"(a) : "l"(p));
    return a;
}
#define CP_ASYNC16(d, s) \
    asm volatile("cp.async.cg.shared.global [%0], [%1], 16;" :: "r"(d), "l"(s) : "memory")
#define CP_COMMIT()      asm volatile("cp.async.commit_group;" ::: "memory")
#define CP_WAIT(n)       asm volatile("cp.async.wait_group %0;" :: "n"(n) : "memory")

__device__ __forceinline__ uint32_t f2tf(float f) {
    uint32_t u;
    asm("cvt.rna.tf32.f32 %0, %1;" : "=r"(u) : "f"(f));
    return u;
}
__device__ __forceinline__ void mma_tf32(float* c, const uint32_t* a, const uint32_t* b) {
    asm volatile(
        "mma.sync.aligned.m16n8k8.row.col.f32.tf32.tf32.f32 "
        "{%0,%1,%2,%3}, {%4,%5,%6,%7}, {%8,%9}, {%0,%1,%2,%3};"
        : "+f"(c[0]), "+f"(c[1]), "+f"(c[2]), "+f"(c[3])
        : "r"(a[0]), "r"(a[1]), "r"(a[2]), "r"(a[3]), "r"(b[0]), "r"(b[1]));
}

// ---------------- tf32 mma.sync NT GEMM: C[M,Nc] = A[M,K] * B[Nc,K]^T ----------------
// CTA tile 128x128, 8 warps (2M x 4N), warp tile 64x32, K-chunk 32, 3-stage cp.async.
// mode 0: store C. mode 1: C = lrelu(acc + bias[col], 0.01).
// mode 2: no C; score[row] += sum_col relu(acc + bias[col]) * w2[col].
__global__ void __launch_bounds__(256, 2) k_mma_gemm(
    const float* __restrict__ A, const float* __restrict__ B, float* __restrict__ C,
    int Nc, int K, int mode,
    const float* __restrict__ bias, const float* __restrict__ w2,
    float* __restrict__ score)
{
    extern __shared__ char dsmem[];
    __shared__ float red[128];

    const int tid  = threadIdx.x;
    const int warp = tid >> 5;
    const int lane = tid & 31;
    const int qid  = lane >> 2;       // group id 0..7
    const int kid  = lane & 3;        // thread in group
    const int wm   = (warp >> 2) * 64;
    const int wn   = (warp & 3) * 32;
    const int row0 = blockIdx.y * 128;
    const int col0 = blockIdx.x * 128;
    const int nch  = K / KC;
    const uint32_t sw = (uint32_t)qid * 16;   // per-thread swizzle constant

    const uint32_t data0 = (smem_u32(dsmem) + 1023u) & ~1023u;

    float c[4][4][4];
#pragma unroll
    for (int i = 0; i < 4; i++)
#pragma unroll
        for (int j = 0; j < 4; j++)
#pragma unroll
            for (int k = 0; k < 4; k++) c[i][j][k] = 0.f;

    auto load_chunk = [&](int ch, int s) {
        const int k0 = ch * KC;
        const uint32_t sa = data0 + (uint32_t)s * STAGE_BYTES;
        const uint32_t sb = sa + ABYTES;
        const float* Ag = A + (size_t)row0 * K + k0;
        const float* Bg = B + (size_t)col0 * K + k0;
#pragma unroll
        for (int w = 0; w < 4; w++) {            // 128 rows x 8 x 16B
            int idx = tid + w * 256;
            int r = idx >> 3, c4 = idx & 7;
            uint32_t off = (uint32_t)r * 128 + (((uint32_t)c4 * 16) ^ (((uint32_t)r & 7) * 16));
            CP_ASYNC16(sa + off, Ag + (size_t)r * K + c4 * 4);
        }
#pragma unroll
        for (int w = 0; w < 4; w++) {
            int idx = tid + w * 256;
            int r = idx >> 3, c4 = idx & 7;
            uint32_t off = (uint32_t)r * 128 + (((uint32_t)c4 * 16) ^ (((uint32_t)r & 7) * 16));
            CP_ASYNC16(sb + off, Bg + (size_t)r * K + c4 * 4);
        }
        CP_COMMIT();
    };

    for (int i = 0; i < STAGES; i++) load_chunk(i, i);

    for (int i = 0; i < nch; i++) {
        const int s = i % STAGES;
        CP_WAIT(STAGES - 1);
        __syncthreads();

        const char* sA = dsmem + ((data0 - smem_u32(dsmem)) + (uint32_t)s * STAGE_BYTES);
        const char* sB = sA + ABYTES;
#pragma unroll
        for (int k8 = 0; k8 < 4; k8++) {
            const uint32_t x0 = (uint32_t)(k8 * 32 + kid * 4);
            const uint32_t off0 = x0 ^ sw;
            const uint32_t off1 = (x0 + 16) ^ sw;
            uint32_t a[4][4], b[4][2];
#pragma unroll
            for (int mt = 0; mt < 4; mt++) {
                const char* p = sA + (size_t)(wm + mt * 16 + qid) * 128;
                a[mt][0] = f2tf(*(const float*)(p + off0));
                a[mt][1] = f2tf(*(const float*)(p + 1024 + off0));
                a[mt][2] = f2tf(*(const float*)(p + off1));
                a[mt][3] = f2tf(*(const float*)(p + 1024 + off1));
            }
#pragma unroll
            for (int nt = 0; nt < 4; nt++) {
                const char* p = sB + (size_t)(wn + nt * 8 + qid) * 128;
                b[nt][0] = f2tf(*(const float*)(p + off0));
                b[nt][1] = f2tf(*(const float*)(p + off1));
            }
#pragma unroll
            for (int mt = 0; mt < 4; mt++)
#pragma unroll
                for (int nt = 0; nt < 4; nt++)
                    mma_tf32(c[mt][nt], a[mt], b[nt]);
        }
        __syncthreads();
        if (i + STAGES < nch) load_chunk(i + STAGES, s);
        else                  CP_COMMIT();
    }

    // ---------------- epilogue ----------------
    if (mode == 2) {
        float bv[8], wv[8];
#pragma unroll
        for (int nt = 0; nt < 4; nt++)
#pragma unroll
            for (int j = 0; j < 2; j++) {
                int col = col0 + wn + nt * 8 + kid * 2 + j;
                bv[nt * 2 + j] = bias[col];
                wv[nt * 2 + j] = w2[col];
            }
        if (tid < 128) red[tid] = 0.f;
        __syncthreads();
#pragma unroll
        for (int mt = 0; mt < 4; mt++)
#pragma unroll
            for (int h = 0; h < 2; h++) {
                float part = 0.f;
#pragma unroll
                for (int nt = 0; nt < 4; nt++)
#pragma unroll
                    for (int j = 0; j < 2; j++) {
                        float v = c[mt][nt][h * 2 + j] + bv[nt * 2 + j];
                        part = fmaf(fmaxf(v, 0.f), wv[nt * 2 + j], part);
                    }
                part += __shfl_xor_sync(0xffffffffu, part, 1);
                part += __shfl_xor_sync(0xffffffffu, part, 2);
                if (kid == 0)
                    atomicAdd(&red[wm + mt * 16 + qid + h * 8], part);
            }
        __syncthreads();
        if (tid < 128) atomicAdd(&score[row0 + tid], red[tid]);
        return;
    }

#pragma unroll
    for (int mt = 0; mt < 4; mt++)
#pragma unroll
        for (int h = 0; h < 2; h++) {
            int row = row0 + wm + mt * 16 + qid + h * 8;
            float* Cp = C + (size_t)row * Nc + col0 + wn;
#pragma unroll
            for (int nt = 0; nt < 4; nt++) {
                float v0 = c[mt][nt][h * 2 + 0];
                float v1 = c[mt][nt][h * 2 + 1];
                int coll = wn + nt * 8 + kid * 2;
                if (mode == 1) {
                    v0 += bias[col0 + coll];
                    v1 += bias[col0 + coll + 1];
                    v0 = v0 >= 0.f ? v0 : 0.01f * v0;
                    v1 = v1 >= 0.f ? v1 : 0.01f * v1;
                }
                *(float2*)(Cp + nt * 8 + kid * 2) = make_float2(v0, v1);
            }
        }
}

// ---------------- small utility kernels ----------------
__global__ void k_zero_gn() {
    int c = threadIdx.x;
    if (c < F) { g_colsum[c] = 0.f; g_colsq[c] = 0.f; }
}

__global__ void k_zero_score() {
    int d = blockIdx.x * blockDim.x + threadIdx.x;
    if (d < DCAT) g_score[d] = 0.f;
}

__global__ void k_init_conv() {
    int idx = blockIdx.x * blockDim.x + threadIdx.x;
    if (idx < NN * F) { g_efeat[idx] = 0.f; g_h[idx] = 0.f; }
    if (idx < NN) {
        g_segsum[idx] = 0.f;
        g_segmax[idx] = 0u;
        g_dege[idx]   = 0.f;
        g_degn[idx]   = 0.f;
    }
}

// ---------------- GraphNorm ----------------
__global__ void k_gn_reduce(const float* __restrict__ X) {
    int c  = threadIdx.x;
    int r0 = blockIdx.x * 64;
    float s = 0.f, q = 0.f;
    for (int i = 0; i < 64; i++) {
        float v = X[(size_t)(r0 + i) * F + c];
        s += v;
        q += v * v;
    }
    atomicAdd(&g_colsum[c], s);
    atomicAdd(&g_colsq[c], q);
}

__global__ void k_gn_apply(const float* __restrict__ X,
                           const float* __restrict__ w,
                           const float* __restrict__ b,
                           const float* __restrict__ ms) {
    int idx = blockIdx.x * blockDim.x + threadIdx.x;
    if (idx >= NN * F) return;
    int c = idx % F;
    float invN  = 1.f / (float)NN;
    float mean  = g_colsum[c] * invN;
    float m     = ms[c];
    float var   = g_colsq[c] * invN - m * (2.f - m) * mean * mean;
    float out   = X[idx] - m * mean;
    g_xn[idx]   = w[c] * out * rsqrtf(var + 1e-5f) + b[c];
}

// ---------------- attention-coefficient GEMVs ----------------
__global__ void k_gemv_att(const float* __restrict__ att) {
    int w    = (blockIdx.x * blockDim.x + threadIdx.x) >> 5;
    int lane = threadIdx.x & 31;
    if (w >= NN) return;
    const float* xr = g_xt + (size_t)w * F;
    const float* er = g_et + (size_t)w * F;
    float s1 = 0.f, s2 = 0.f;
    for (int i = lane; i < F; i += 32) {
        s1 = fmaf(xr[i], att[i],     s1);
        s2 = fmaf(er[i], att[F + i], s2);
    }
#pragma unroll
    for (int off = 16; off; off >>= 1) {
        s1 += __shfl_xor_sync(0xffffffffu, s1, off);
        s2 += __shfl_xor_sync(0xffffffffu, s2, off);
    }
    if (lane == 0) { g_ax[w] = s1; g_ae[w] = s2; }
}

// ---------------- edge kernels ----------------
__device__ __forceinline__ unsigned fkey(float f) {
    unsigned k = __float_as_uint(f);
    return (k & 0x80000000u) ? ~k : (k | 0x80000000u);
}
__device__ __forceinline__ float fkey_inv(unsigned k) {
    return (k & 0x80000000u) ? __uint_as_float(k & 0x7FFFFFFFu) : __uint_as_float(~k);
}

__global__ void k_edge1(const int* __restrict__ ei) {
    int e = blockIdx.x * blockDim.x + threadIdx.x;
    if (e >= NNZ) return;
    int r = ei[e], c = ei[NNZ + e];
    float a = g_ax[r] + g_ae[c];
    a = a >= 0.f ? a : 0.2f * a;
    g_alpha[e] = a;
    atomicMax(&g_segmax[c], fkey(a));
    atomicAdd(&g_degn[r], 1.f);
    atomicAdd(&g_dege[c], 1.f);
}

__global__ void k_edge2(const int* __restrict__ ei) {
    int e = blockIdx.x * blockDim.x + threadIdx.x;
    if (e >= NNZ) return;
    int c = ei[NNZ + e];
    float m  = fkey_inv(g_segmax[c]);
    float ex = expf(g_alpha[e] - m);
    g_alpha[e] = ex;
    atomicAdd(&g_segsum[c], ex);
}

__global__ void k_edge3(const int* __restrict__ ei) {
    int e = blockIdx.x;
    int r = ei[e], c = ei[NNZ + e];
    float de   = g_dege[c];
    float bn   = de > 0.f ? 1.f / de : 0.f;
    float coef = bn * (g_alpha[e] / (g_segsum[c] + 1e-16f));
    int f4 = threadIdx.x * 4;
    float4 v = *(const float4*)&g_xt[(size_t)r * F + f4];
    float* dst = &g_efeat[(size_t)c * F + f4];
    atomicAdd(dst + 0, coef * v.x);
    atomicAdd(dst + 1, coef * v.y);
    atomicAdd(dst + 2, coef * v.z);
    atomicAdd(dst + 3, coef * v.w);
}

__global__ void k_edge4(const int* __restrict__ ei) {
    int e = blockIdx.x;
    int r = ei[e], c = ei[NNZ + e];
    float dn    = g_degn[r];
    float dcoef = dn > 0.f ? 1.f / dn : 0.f;
    float coef  = dcoef * (g_alpha[e] / (g_segsum[c] + 1e-16f));
    int f4 = threadIdx.x * 4;
    float4 v = *(const float4*)&g_efeat[(size_t)c * F + f4];
    float* dst = &g_h[(size_t)r * F + f4];
    atomicAdd(dst + 0, coef * v.x);
    atomicAdd(dst + 1, coef * v.y);
    atomicAdd(dst + 2, coef * v.z);
    atomicAdd(dst + 3, coef * v.w);
}

__global__ void k_bias_lrelu(const float* __restrict__ b) {
    int idx = blockIdx.x * blockDim.x + threadIdx.x;
    if (idx >= NN * F) return;
    int c = idx % F;
    float v = g_h[idx] + b[c];
    g_h[idx] = v >= 0.f ? v : 0.01f * v;
}

// ---------------- transpose src[NN,C] -> dst[c*NN + r] ----------------
__global__ void k_transpose(const float* __restrict__ src, int C, float* __restrict__ dst) {
    __shared__ float t[32][33];
    int c0 = blockIdx.x * 32, r0 = blockIdx.y * 32;
    int tx = threadIdx.x, ty = threadIdx.y;
#pragma unroll
    for (int i = 0; i < 4; i++)
        t[ty + 8 * i][tx] = src[(size_t)(r0 + ty + 8 * i) * C + c0 + tx];
    __syncthreads();
#pragma unroll
    for (int i = 0; i < 4; i++)
        dst[(size_t)(c0 + ty + 8 * i) * NN + r0 + tx] = t[tx][ty + 8 * i];
}

// ---------------- score finalize + folded classifier ----------------
__global__ void k_score_final(const float* __restrict__ b2, const float* __restrict__ center) {
    int d = blockIdx.x * blockDim.x + threadIdx.x;
    if (d >= DCAT) return;
    float r = g_score[d] + b2[0];
    float sg = 1.f / (1.f + expf(-r));
    g_score[d] = sg - center[d];
}

__global__ void k_wp(const float* __restrict__ clsW) {
    int idx = blockIdx.x * blockDim.x + threadIdx.x;
    if (idx >= OUTD * DCAT) return;
    g_wp[idx] = clsW[idx] * g_score[idx % DCAT];
}

__global__ void k_logits(const float* __restrict__ x, const float* __restrict__ clsb,
                         float* __restrict__ out) {
    int n    = (blockIdx.x * blockDim.x + threadIdx.x) >> 5;
    int lane = threadIdx.x & 31;
    if (n >= NN) return;
    float acc[OUTD];
#pragma unroll
    for (int o = 0; o < OUTD; o++) acc[o] = 0.f;

    const float* xr = x + (size_t)n * F;
#pragma unroll
    for (int it = 0; it < 6; it++) {
        int i = lane * 4 + it * 128;
        float4 v = *(const float4*)&xr[i];
#pragma unroll
        for (int o = 0; o < OUTD; o++) {
            float4 w = *(const float4*)&g_wp[o * DCAT + i];
            acc[o] += v.x * w.x + v.y * w.y + v.z * w.z + v.w * w.w;
        }
    }
    const float* o1 = g_out1 + (size_t)n * HIDD;
#pragma unroll
    for (int it = 0; it < 3; it++) {
        int i = lane * 4 + it * 128;
        float4 v = *(const float4*)&o1[i];
#pragma unroll
        for (int o = 0; o < OUTD; o++) {
            float4 w = *(const float4*)&g_wp[o * DCAT + F + i];
            acc[o] += v.x * w.x + v.y * w.y + v.z * w.z + v.w * w.w;
        }
    }
    const float* o2 = g_out2 + (size_t)n * HIDD;
#pragma unroll
    for (int it = 0; it < 3; it++) {
        int i = lane * 4 + it * 128;
        float4 v = *(const float4*)&o2[i];
#pragma unroll
        for (int o = 0; o < OUTD; o++) {
            float4 w = *(const float4*)&g_wp[o * DCAT + F + HIDD + i];
            acc[o] += v.x * w.x + v.y * w.y + v.z * w.z + v.w * w.w;
        }
    }
#pragma unroll
    for (int o = 0; o < OUTD; o++) {
        float v = acc[o];
#pragma unroll
        for (int off = 16; off; off >>= 1) v += __shfl_xor_sync(0xffffffffu, v, off);
        if (lane == 0) out[(size_t)n * OUTD + o] = v + clsb[o];
    }
}

// ---------------- host-side driver ----------------
static void run_conv(const float* feat_in, const int* ei, const float* eattr,
                     const float* gw, const float* gb, const float* gms,
                     const float* W, const float* att, const float* hb,
                     float* p_xn, float* p_xt, float* p_et)
{
    k_zero_gn<<<1, 768>>>();
    k_gn_reduce<<<NN / 64, 768>>>(feat_in);
    k_gn_apply<<<NN * F / 256, 256>>>(feat_in, gw, gb, gms);
    k_init_conv<<<NN * F / 256, 256>>>();
    k_mma_gemm<<<dim3(F / 128, NN / 128), 256, SMEM_GEMM>>>(
        p_xn, W, p_xt, F, F, 0, nullptr, nullptr, nullptr);
    k_mma_gemm<<<dim3(F / 128, NN / 128), 256, SMEM_GEMM>>>(
        eattr, W, p_et, F, F, 0, nullptr, nullptr, nullptr);
    k_gemv_att<<<NN / 8, 256>>>(att);
    k_edge1<<<NNZ / 256, 256>>>(ei);
    k_edge2<<<NNZ / 256, 256>>>(ei);
    k_edge3<<<NNZ, 192>>>(ei);
    k_edge4<<<NNZ, 192>>>(ei);
    k_bias_lrelu<<<NN * F / 256, 256>>>(hb);
}

extern "C" void kernel_launch(void* const* d_in, const int* in_sizes, int n_in,
                              void* d_out, int out_size) {
    const float* x       = (const float*)d_in[0];
    const int*   ei      = (const int*)  d_in[1];
    const float* eattr   = (const float*)d_in[2];
    const float* gn1_w   = (const float*)d_in[3];
    const float* gn1_b   = (const float*)d_in[4];
    const float* gn1_ms  = (const float*)d_in[5];
    const float* gn2_w   = (const float*)d_in[6];
    const float* gn2_b   = (const float*)d_in[7];
    const float* gn2_ms  = (const float*)d_in[8];
    const float* hg1_W   = (const float*)d_in[9];
    const float* hg1_att = (const float*)d_in[10];
    const float* hg1_b   = (const float*)d_in[11];
    const float* hg2_W   = (const float*)d_in[12];
    const float* hg2_att = (const float*)d_in[13];
    const float* hg2_b   = (const float*)d_in[14];
    const float* fc1_W   = (const float*)d_in[15];
    const float* fc1_b   = (const float*)d_in[16];
    const float* fc2_W   = (const float*)d_in[17];
    const float* fc2_b   = (const float*)d_in[18];
    const float* attn_W1 = (const float*)d_in[19];
    const float* attn_b1 = (const float*)d_in[20];
    const float* attn_W2 = (const float*)d_in[21];
    const float* attn_b2 = (const float*)d_in[22];
    const float* cls_W   = (const float*)d_in[23];
    const float* cls_b   = (const float*)d_in[24];
    const float* center  = (const float*)d_in[25];
    float*       out     = (float*)d_out;

    cudaFuncSetAttribute(k_mma_gemm, cudaFuncAttributeMaxDynamicSharedMemorySize, SMEM_GEMM);

    float *p_xn, *p_xt, *p_et, *p_h, *p_out1, *p_out2, *p_catT, *p_score;
    cudaGetSymbolAddress((void**)&p_xn,    g_xn);
    cudaGetSymbolAddress((void**)&p_xt,    g_xt);
    cudaGetSymbolAddress((void**)&p_et,    g_et);
    cudaGetSymbolAddress((void**)&p_h,     g_h);
    cudaGetSymbolAddress((void**)&p_out1,  g_out1);
    cudaGetSymbolAddress((void**)&p_out2,  g_out2);
    cudaGetSymbolAddress((void**)&p_catT,  g_catT);
    cudaGetSymbolAddress((void**)&p_score, g_score);

    // ---- conv1 + fc1 ----
    run_conv(x, ei, eattr, gn1_w, gn1_b, gn1_ms, hg1_W, hg1_att, hg1_b, p_xn, p_xt, p_et);
    k_mma_gemm<<<dim3(HIDD / 128, NN / 128), 256, SMEM_GEMM>>>(
        p_h, fc1_W, p_out1, HIDD, F, 1, fc1_b, nullptr, nullptr);

    // ---- conv2 (graphnorm reads g_h=h1 before re-zero) + fc2 ----
    run_conv(p_h, ei, eattr, gn2_w, gn2_b, gn2_ms, hg2_W, hg2_att, hg2_b, p_xn, p_xt, p_et);
    k_mma_gemm<<<dim3(HIDD / 128, NN / 128), 256, SMEM_GEMM>>>(
        p_h, fc2_W, p_out2, HIDD, F, 1, fc2_b, nullptr, nullptr);

    // ---- catT = [x; out1; out2]^T (feature-major, node-contiguous) ----
    k_transpose<<<dim3(F / 32,    NN / 32), dim3(32, 8)>>>(x,      F,    p_catT);
    k_transpose<<<dim3(HIDD / 32, NN / 32), dim3(32, 8)>>>(p_out1, HIDD, p_catT + (size_t)F * NN);
    k_transpose<<<dim3(HIDD / 32, NN / 32), dim3(32, 8)>>>(p_out2, HIDD, p_catT + (size_t)(F + HIDD) * NN);

    // ---- attention: score[d] = sum_j relu(catT@W1^T + b1)[d,j] * W2[j] (fused epilogue) ----
    k_zero_score<<<(DCAT + 255) / 256, 256>>>();
    k_mma_gemm<<<dim3(NN / 128, DCAT / 128), 256, SMEM_GEMM>>>(
        p_catT, attn_W1, nullptr, NN, NN, 2, attn_b1, attn_W2, p_score);
    k_score_final<<<(DCAT + 255) / 256, 256>>>(attn_b2, center);

    // ---- classifier with score folded into weights ----
    k_wp<<<(OUTD * DCAT + 255) / 256, 256>>>(cls_W);
    k_logits<<<NN * 32 / 256, 256>>>(x, cls_b, out);
}

// round 7
// speedup vs baseline: 4.0096x; 1.5773x over previous
#include <cuda_runtime.h>
#include <cstdint>

#define NN   8192
#define F    768
#define HIDD 384
#define OUTD 10
#define NNZ  (NN * 16)
#define DCAT (F + 2 * HIDD)

#define KC      32                 // fp32 per K-chunk (128 B per smem row)
#define STAGES  3
#define ABYTES  (128 * 128)        // A tile: 128 rows x 128 B

// ---------------- scratch (device globals; no allocation allowed) ----------------
__device__ float    g_xn[NN * F];
__device__ float    g_xt[NN * F];
__device__ float    g_et[NN * F];
__device__ float    g_eat[NN * F];      // eattr pre-converted to tf32 bits
__device__ float    g_efeat[NN * F];
__device__ float    g_h[NN * F];
__device__ float    g_out1[NN * HIDD];
__device__ float    g_out2[NN * HIDD];
__device__ float    g_catT[(size_t)DCAT * NN];
__device__ float    g_w1t[(size_t)NN * NN];   // attn_W1 tf32 bits
__device__ float    g_wt[F * F];              // hg W tf32 bits
__device__ float    g_fwt[HIDD * F];          // fc W tf32 bits
__device__ float    g_alpha[NNZ];
__device__ float    g_ax[NN];
__device__ float    g_ae[NN];
__device__ float    g_score[DCAT];
__device__ float    g_wp[OUTD * DCAT];
// CSR structures (built once; edge_index identical for both convs)
__device__ int      g_cnt_c[NN], g_cnt_r[NN];
__device__ int      g_cur_c[NN], g_cur_r[NN];
__device__ int      g_off_c[NN + 1], g_off_r[NN + 1];
__device__ int      g_perm_c[NNZ], g_perm_r[NNZ];

// ---------------- PTX helpers (plain sm_103-safe) ----------------
__device__ __forceinline__ uint32_t smem_u32(const void* p) {
    uint32_t a;
    asm("{ .reg .u64 t; cvta.to.shared.u64 t, %1; cvt.u32.u64 %0, t; }" : "=r"(a) : "l"(p));
    return a;
}
#define CP_ASYNC16(d, s) \
    asm volatile("cp.async.cg.shared.global [%0], [%1], 16;" :: "r"(d), "l"(s) : "memory")
#define CP_COMMIT()      asm volatile("cp.async.commit_group;" ::: "memory")
#define CP_WAIT(n)       asm volatile("cp.async.wait_group %0;" :: "n"(n) : "memory")

__device__ __forceinline__ uint32_t f2tf(float f) {
    uint32_t u;
    asm("cvt.rna.tf32.f32 %0, %1;" : "=r"(u) : "f"(f));
    return u;
}
__device__ __forceinline__ float round_tf(float f) { return __uint_as_float(f2tf(f)); }

__device__ __forceinline__ void mma_tf32(float* c, const uint32_t* a, const uint32_t* b) {
    asm volatile(
        "mma.sync.aligned.m16n8k8.row.col.f32.tf32.tf32.f32 "
        "{%0,%1,%2,%3}, {%4,%5,%6,%7}, {%8,%9}, {%0,%1,%2,%3};"
        : "+f"(c[0]), "+f"(c[1]), "+f"(c[2]), "+f"(c[3])
        : "r"(a[0]), "r"(a[1]), "r"(a[2]), "r"(a[3]), "r"(b[0]), "r"(b[1]));
}

// ---------------- tf32 mma.sync NT GEMM: C[M,Nc] = A[M,K] * B[Nc,K]^T ----------------
// Inputs are PRE-ROUNDED tf32 bit patterns (no cvt in hot loop).
// CTA tile 128 x NT, 8 warps (2M x 4N), warp tile 64 x (NT/4). K-chunk 32 fp32.
// mode 0: store C. mode 1: C = lrelu(acc + bias[col], 0.01).
// mode 2: no C; score[row] += sum_col relu(acc + bias[col]) * w2[col].
template <int NT>
__global__ void __launch_bounds__(256, 1) k_gemm(
    const float* __restrict__ A, const float* __restrict__ B, float* __restrict__ C,
    int Nc, int K, int mode,
    const float* __restrict__ bias, const float* __restrict__ w2,
    float* __restrict__ score)
{
    constexpr int N8     = NT / 32;            // n8 tiles per warp (8 or 4)
    constexpr int BBYTES = NT * 128;
    constexpr int STB    = ABYTES + BBYTES;
    extern __shared__ char dsmem[];
    __shared__ float red[128];

    const int tid  = threadIdx.x;
    const int warp = tid >> 5;
    const int lane = tid & 31;
    const int qid  = lane >> 2;
    const int kid  = lane & 3;
    const int wm   = (warp >> 2) * 64;
    const int wn   = (warp & 3) * (NT / 4);
    const int row0 = blockIdx.y * 128;
    const int col0 = blockIdx.x * NT;
    const int nch  = K / KC;
    const uint32_t sw = (uint32_t)qid * 16;
    const uint32_t sm0   = smem_u32(dsmem);
    const uint32_t data0 = (sm0 + 1023u) & ~1023u;

    float c[4][N8][4];
#pragma unroll
    for (int i = 0; i < 4; i++)
#pragma unroll
        for (int j = 0; j < N8; j++)
#pragma unroll
            for (int k = 0; k < 4; k++) c[i][j][k] = 0.f;

    auto load_chunk = [&](int ch, int s) {
        const int k0 = ch * KC;
        const uint32_t sa = data0 + (uint32_t)s * STB;
        const uint32_t sb = sa + ABYTES;
        const float* Ag = A + (size_t)row0 * K + k0;
        const float* Bg = B + (size_t)col0 * K + k0;
#pragma unroll
        for (int w = 0; w < 4; w++) {
            int idx = tid + w * 256;
            int r = idx >> 3, c4 = idx & 7;
            uint32_t off = (uint32_t)r * 128 + (((uint32_t)c4 * 16) ^ (((uint32_t)r & 7) * 16));
            CP_ASYNC16(sa + off, Ag + (size_t)r * K + c4 * 4);
        }
#pragma unroll
        for (int w = 0; w < NT / 32; w++) {
            int idx = tid + w * 256;
            int r = idx >> 3, c4 = idx & 7;
            uint32_t off = (uint32_t)r * 128 + (((uint32_t)c4 * 16) ^ (((uint32_t)r & 7) * 16));
            CP_ASYNC16(sb + off, Bg + (size_t)r * K + c4 * 4);
        }
        CP_COMMIT();
    };

    for (int i = 0; i < STAGES; i++) load_chunk(i, i);

    for (int i = 0; i < nch; i++) {
        const int s = i % STAGES;
        CP_WAIT(STAGES - 1);
        __syncthreads();

        const char* sA = dsmem + ((data0 - sm0) + (uint32_t)s * STB);
        const char* sB = sA + ABYTES;
#pragma unroll
        for (int k8 = 0; k8 < 4; k8++) {
            const uint32_t x0   = (uint32_t)(k8 * 32 + kid * 4);
            const uint32_t off0 = x0 ^ sw;
            const uint32_t off1 = (x0 + 16) ^ sw;
            uint32_t a[4][4], b[N8][2];
#pragma unroll
            for (int mt = 0; mt < 4; mt++) {
                const char* p = sA + (size_t)(wm + mt * 16 + qid) * 128;
                a[mt][0] = *(const uint32_t*)(p + off0);
                a[mt][1] = *(const uint32_t*)(p + 1024 + off0);
                a[mt][2] = *(const uint32_t*)(p + off1);
                a[mt][3] = *(const uint32_t*)(p + 1024 + off1);
            }
#pragma unroll
            for (int nt = 0; nt < N8; nt++) {
                const char* p = sB + (size_t)(wn + nt * 8 + qid) * 128;
                b[nt][0] = *(const uint32_t*)(p + off0);
                b[nt][1] = *(const uint32_t*)(p + off1);
            }
#pragma unroll
            for (int mt = 0; mt < 4; mt++)
#pragma unroll
                for (int nt = 0; nt < N8; nt++)
                    mma_tf32(c[mt][nt], a[mt], b[nt]);
        }
        __syncthreads();
        if (i + STAGES < nch) load_chunk(i + STAGES, s);
        else                  CP_COMMIT();
    }

    // ---------------- epilogue ----------------
    if (mode == 2) {
        float bv[N8 * 2], wv[N8 * 2];
#pragma unroll
        for (int nt = 0; nt < N8; nt++)
#pragma unroll
            for (int j = 0; j < 2; j++) {
                int col = col0 + wn + nt * 8 + kid * 2 + j;
                bv[nt * 2 + j] = bias[col];
                wv[nt * 2 + j] = w2[col];
            }
        if (tid < 128) red[tid] = 0.f;
        __syncthreads();
#pragma unroll
        for (int mt = 0; mt < 4; mt++)
#pragma unroll
            for (int h = 0; h < 2; h++) {
                float part = 0.f;
#pragma unroll
                for (int nt = 0; nt < N8; nt++)
#pragma unroll
                    for (int j = 0; j < 2; j++) {
                        float v = c[mt][nt][h * 2 + j] + bv[nt * 2 + j];
                        part = fmaf(fmaxf(v, 0.f), wv[nt * 2 + j], part);
                    }
                part += __shfl_xor_sync(0xffffffffu, part, 1);
                part += __shfl_xor_sync(0xffffffffu, part, 2);
                if (kid == 0)
                    atomicAdd(&red[wm + mt * 16 + qid + h * 8], part);
            }
        __syncthreads();
        if (tid < 128) atomicAdd(&score[row0 + tid], red[tid]);
        return;
    }

#pragma unroll
    for (int mt = 0; mt < 4; mt++)
#pragma unroll
        for (int h = 0; h < 2; h++) {
            int row = row0 + wm + mt * 16 + qid + h * 8;
            float* Cp = C + (size_t)row * Nc + col0 + wn;
#pragma unroll
            for (int nt = 0; nt < N8; nt++) {
                float v0 = c[mt][nt][h * 2 + 0];
                float v1 = c[mt][nt][h * 2 + 1];
                int coll = wn + nt * 8 + kid * 2;
                if (mode == 1) {
                    v0 += bias[col0 + coll];
                    v1 += bias[col0 + coll + 1];
                    v0 = v0 >= 0.f ? v0 : 0.01f * v0;
                    v1 = v1 >= 0.f ? v1 : 0.01f * v1;
                }
                *(float2*)(Cp + nt * 8 + kid * 2) = make_float2(v0, v1);
            }
        }
}

// ---------------- tf32 pre-conversion ----------------
__global__ void k_cvt4(const float4* __restrict__ src, float4* __restrict__ dst, int n4) {
    int i = blockIdx.x * blockDim.x + threadIdx.x;
    if (i >= n4) return;
    float4 v = src[i];
    v.x = round_tf(v.x); v.y = round_tf(v.y); v.z = round_tf(v.z); v.w = round_tf(v.w);
    dst[i] = v;
}

// ---------------- CSR build (once; edge_index shared by both convs) ----------------
__global__ void k_csr_zero() {
    int i = blockIdx.x * blockDim.x + threadIdx.x;
    if (i < NN) { g_cnt_c[i] = 0; g_cnt_r[i] = 0; g_cur_c[i] = 0; g_cur_r[i] = 0; }
}
__global__ void k_csr_count(const int* __restrict__ ei) {
    int e = blockIdx.x * blockDim.x + threadIdx.x;
    if (e >= NNZ) return;
    atomicAdd(&g_cnt_c[ei[NNZ + e]], 1);
    atomicAdd(&g_cnt_r[ei[e]], 1);
}
// exclusive scan of 8192 ints, single block of 1024 threads
__global__ void k_scan(const int* __restrict__ cnt, int* __restrict__ off) {
    __shared__ int part[1024];
    int t = threadIdx.x;
    int loc[8];
    int s = 0;
#pragma unroll
    for (int i = 0; i < 8; i++) { loc[i] = s; s += cnt[t * 8 + i]; }
    part[t] = s;
    __syncthreads();
    for (int d = 1; d < 1024; d <<= 1) {
        int v = (t >= d) ? part[t - d] : 0;
        __syncthreads();
        part[t] += v;
        __syncthreads();
    }
    int base = (t == 0) ? 0 : part[t - 1];
#pragma unroll
    for (int i = 0; i < 8; i++) off[t * 8 + i] = base + loc[i];
    if (t == 1023) off[NN] = part[1023];
}
__global__ void k_csr_place(const int* __restrict__ ei) {
    int e = blockIdx.x * blockDim.x + threadIdx.x;
    if (e >= NNZ) return;
    int r = ei[e], c = ei[NNZ + e];
    int pc = atomicAdd(&g_cur_c[c], 1);
    g_perm_c[g_off_c[c] + pc] = e;
    int pr = atomicAdd(&g_cur_r[r], 1);
    g_perm_r[g_off_r[r] + pr] = e;
}

// ---------------- small utility kernels ----------------
__global__ void k_zero_gn(float* __restrict__ colsum, float* __restrict__ colsq) {
    int c = threadIdx.x;
    if (c < F) { colsum[c] = 0.f; colsq[c] = 0.f; }
}
__device__ float g_colsum[F];
__device__ float g_colsq[F];

__global__ void k_zero_score() {
    int d = blockIdx.x * blockDim.x + threadIdx.x;
    if (d < DCAT) g_score[d] = 0.f;
}

// ---------------- GraphNorm ----------------
__global__ void k_gn_reduce(const float* __restrict__ X) {
    int c  = threadIdx.x;
    int r0 = blockIdx.x * 64;
    float s = 0.f, q = 0.f;
    for (int i = 0; i < 64; i++) {
        float v = X[(size_t)(r0 + i) * F + c];
        s += v;
        q += v * v;
    }
    atomicAdd(&g_colsum[c], s);
    atomicAdd(&g_colsq[c], q);
}

__global__ void k_gn_apply(const float* __restrict__ X,
                           const float* __restrict__ w,
                           const float* __restrict__ b,
                           const float* __restrict__ ms) {
    int idx = blockIdx.x * blockDim.x + threadIdx.x;
    if (idx >= NN * F) return;
    int c = idx % F;
    float invN  = 1.f / (float)NN;
    float mean  = g_colsum[c] * invN;
    float m     = ms[c];
    float var   = g_colsq[c] * invN - m * (2.f - m) * mean * mean;
    float outv  = X[idx] - m * mean;
    g_xn[idx]   = round_tf(w[c] * outv * rsqrtf(var + 1e-5f) + b[c]);  // tf32: GEMM input
}

// ---------------- attention-coefficient GEMVs ----------------
__global__ void k_gemv_att(const float* __restrict__ att) {
    int w    = (blockIdx.x * blockDim.x + threadIdx.x) >> 5;
    int lane = threadIdx.x & 31;
    if (w >= NN) return;
    const float* xr = g_xt + (size_t)w * F;
    const float* er = g_et + (size_t)w * F;
    float s1 = 0.f, s2 = 0.f;
    for (int i = lane; i < F; i += 32) {
        s1 = fmaf(xr[i], att[i],     s1);
        s2 = fmaf(er[i], att[F + i], s2);
    }
#pragma unroll
    for (int off = 16; off; off >>= 1) {
        s1 += __shfl_xor_sync(0xffffffffu, s1, off);
        s2 += __shfl_xor_sync(0xffffffffu, s2, off);
    }
    if (lane == 0) { g_ax[w] = s1; g_ae[w] = s2; }
}

// ---------------- fused per-hyperedge softmax (warp per segment, no atomics) ----------------
__global__ void k_seg_softmax(const int* __restrict__ ei) {
    int w    = (blockIdx.x * blockDim.x + threadIdx.x) >> 5;
    int lane = threadIdx.x & 31;
    if (w >= NN) return;
    int s = g_off_c[w], n = g_off_c[w + 1] - s;
    if (n == 0) return;
    float aec = g_ae[w];
    float m = -3.4e38f;
    for (int i = lane; i < n; i += 32) {
        int e = g_perm_c[s + i];
        float a = g_ax[ei[e]] + aec;
        a = a >= 0.f ? a : 0.2f * a;
        g_alpha[e] = a;
        m = fmaxf(m, a);
    }
#pragma unroll
    for (int o = 16; o; o >>= 1) m = fmaxf(m, __shfl_xor_sync(0xffffffffu, m, o));
    float sum = 0.f;
    for (int i = lane; i < n; i += 32) {
        int e = g_perm_c[s + i];
        float ex = expf(g_alpha[e] - m);
        g_alpha[e] = ex;
        sum += ex;
    }
#pragma unroll
    for (int o = 16; o; o >>= 1) sum += __shfl_xor_sync(0xffffffffu, sum, o);
    float inv = 1.f / (sum + 1e-16f);
    for (int i = lane; i < n; i += 32) g_alpha[g_perm_c[s + i]] *= inv;
}

// ---------------- atomic-free scatters: block per segment, register accumulation ----------------
#define SCH 64
__global__ void k_scatter_e(const int* __restrict__ ei) {   // node -> hyperedge
    __shared__ float scoef[SCH];
    __shared__ int   sidx[SCH];
    int c = blockIdx.x;
    int s = g_off_c[c], end = g_off_c[c + 1];
    int n = end - s;
    float bn = n > 0 ? 1.f / (float)n : 0.f;
    int f = threadIdx.x * 4;
    float4 acc = make_float4(0.f, 0.f, 0.f, 0.f);
    while (s < end) {
        int chunk = min(SCH, end - s);
        __syncthreads();
        if ((int)threadIdx.x < chunk) {
            int e = g_perm_c[s + threadIdx.x];
            scoef[threadIdx.x] = bn * g_alpha[e];
            sidx[threadIdx.x]  = ei[e];                 // row
        }
        __syncthreads();
        for (int j = 0; j < chunk; j++) {
            float cf = scoef[j];
            float4 v = *(const float4*)&g_xt[(size_t)sidx[j] * F + f];
            acc.x = fmaf(cf, v.x, acc.x);
            acc.y = fmaf(cf, v.y, acc.y);
            acc.z = fmaf(cf, v.z, acc.z);
            acc.w = fmaf(cf, v.w, acc.w);
        }
        s += chunk;
    }
    *(float4*)&g_efeat[(size_t)c * F + f] = acc;
}

__global__ void k_scatter_n(const int* __restrict__ ei, const float* __restrict__ bias) {
    __shared__ float scoef[SCH];
    __shared__ int   sidx[SCH];
    int r = blockIdx.x;
    int s = g_off_r[r], end = g_off_r[r + 1];
    int n = end - s;
    float dn = n > 0 ? 1.f / (float)n : 0.f;
    int f = threadIdx.x * 4;
    float4 acc = make_float4(0.f, 0.f, 0.f, 0.f);
    while (s < end) {
        int chunk = min(SCH, end - s);
        __syncthreads();
        if ((int)threadIdx.x < chunk) {
            int e = g_perm_r[s + threadIdx.x];
            scoef[threadIdx.x] = dn * g_alpha[e];
            sidx[threadIdx.x]  = ei[NNZ + e];           // col
        }
        __syncthreads();
        for (int j = 0; j < chunk; j++) {
            float cf = scoef[j];
            float4 v = *(const float4*)&g_efeat[(size_t)sidx[j] * F + f];
            acc.x = fmaf(cf, v.x, acc.x);
            acc.y = fmaf(cf, v.y, acc.y);
            acc.z = fmaf(cf, v.z, acc.z);
            acc.w = fmaf(cf, v.w, acc.w);
        }
        s += chunk;
    }
    // fused: + bias, leaky relu 0.01, tf32 round (h feeds only GEMMs / GN / stats)
    float4 b4 = *(const float4*)&bias[f];
    acc.x += b4.x; acc.y += b4.y; acc.z += b4.z; acc.w += b4.w;
    acc.x = acc.x >= 0.f ? acc.x : 0.01f * acc.x;
    acc.y = acc.y >= 0.f ? acc.y : 0.01f * acc.y;
    acc.z = acc.z >= 0.f ? acc.z : 0.01f * acc.z;
    acc.w = acc.w >= 0.f ? acc.w : 0.01f * acc.w;
    acc.x = round_tf(acc.x); acc.y = round_tf(acc.y);
    acc.z = round_tf(acc.z); acc.w = round_tf(acc.w);
    *(float4*)&g_h[(size_t)r * F + f] = acc;
}

// ---------------- transpose src[NN,C] -> dst[c*NN + r], tf32-rounded (GEMM input) ----------------
__global__ void k_transpose(const float* __restrict__ src, int C, float* __restrict__ dst) {
    __shared__ float t[32][33];
    int c0 = blockIdx.x * 32, r0 = blockIdx.y * 32;
    int tx = threadIdx.x, ty = threadIdx.y;
#pragma unroll
    for (int i = 0; i < 4; i++)
        t[ty + 8 * i][tx] = src[(size_t)(r0 + ty + 8 * i) * C + c0 + tx];
    __syncthreads();
#pragma unroll
    for (int i = 0; i < 4; i++)
        dst[(size_t)(c0 + ty + 8 * i) * NN + r0 + tx] = round_tf(t[tx][ty + 8 * i]);
}

// ---------------- score finalize + folded classifier ----------------
__global__ void k_score_final(const float* __restrict__ b2, const float* __restrict__ center) {
    int d = blockIdx.x * blockDim.x + threadIdx.x;
    if (d >= DCAT) return;
    float r = g_score[d] + b2[0];
    float sg = 1.f / (1.f + expf(-r));
    g_score[d] = sg - center[d];
}

__global__ void k_wp(const float* __restrict__ clsW) {
    int idx = blockIdx.x * blockDim.x + threadIdx.x;
    if (idx >= OUTD * DCAT) return;
    g_wp[idx] = clsW[idx] * g_score[idx % DCAT];
}

__global__ void k_logits(const float* __restrict__ x, const float* __restrict__ clsb,
                         float* __restrict__ out) {
    int n    = (blockIdx.x * blockDim.x + threadIdx.x) >> 5;
    int lane = threadIdx.x & 31;
    if (n >= NN) return;
    float acc[OUTD];
#pragma unroll
    for (int o = 0; o < OUTD; o++) acc[o] = 0.f;

    const float* xr = x + (size_t)n * F;
#pragma unroll
    for (int it = 0; it < 6; it++) {
        int i = lane * 4 + it * 128;
        float4 v = *(const float4*)&xr[i];
#pragma unroll
        for (int o = 0; o < OUTD; o++) {
            float4 w = *(const float4*)&g_wp[o * DCAT + i];
            acc[o] += v.x * w.x + v.y * w.y + v.z * w.z + v.w * w.w;
        }
    }
    const float* o1 = g_out1 + (size_t)n * HIDD;
#pragma unroll
    for (int it = 0; it < 3; it++) {
        int i = lane * 4 + it * 128;
        float4 v = *(const float4*)&o1[i];
#pragma unroll
        for (int o = 0; o < OUTD; o++) {
            float4 w = *(const float4*)&g_wp[o * DCAT + F + i];
            acc[o] += v.x * w.x + v.y * w.y + v.z * w.z + v.w * w.w;
        }
    }
    const float* o2 = g_out2 + (size_t)n * HIDD;
#pragma unroll
    for (int it = 0; it < 3; it++) {
        int i = lane * 4 + it * 128;
        float4 v = *(const float4*)&o2[i];
#pragma unroll
        for (int o = 0; o < OUTD; o++) {
            float4 w = *(const float4*)&g_wp[o * DCAT + F + HIDD + i];
            acc[o] += v.x * w.x + v.y * w.y + v.z * w.z + v.w * w.w;
        }
    }
#pragma unroll
    for (int o = 0; o < OUTD; o++) {
        float v = acc[o];
#pragma unroll
        for (int off = 16; off; off >>= 1) v += __shfl_xor_sync(0xffffffffu, v, off);
        if (lane == 0) out[(size_t)n * OUTD + o] = v + clsb[o];
    }
}

// ---------------- host-side driver ----------------
static const int SMEM256 = STAGES * (ABYTES + 256 * 128) + 1024;  // 148480
static const int SMEM128 = STAGES * (ABYTES + 128 * 128) + 1024;  //  99328

static void run_conv(const float* feat_in, const int* ei,
                     const float* gw, const float* gb, const float* gms,
                     const float* W, const float* att, const float* hb,
                     float* p_xn, float* p_xt, float* p_et, float* p_eat,
                     float* p_wt, float* p_colsum, float* p_colsq)
{
    k_zero_gn<<<1, 768>>>(p_colsum, p_colsq);
    k_gn_reduce<<<NN / 64, 768>>>(feat_in);
    k_gn_apply<<<NN * F / 256, 256>>>(feat_in, gw, gb, gms);
    k_cvt4<<<(F * F / 4 + 255) / 256, 256>>>((const float4*)W, (float4*)p_wt, F * F / 4);
    k_gemm<256><<<dim3(F / 256, NN / 128), 256, SMEM256>>>(
        p_xn, p_wt, p_xt, F, F, 0, nullptr, nullptr, nullptr);
    k_gemm<256><<<dim3(F / 256, NN / 128), 256, SMEM256>>>(
        p_eat, p_wt, p_et, F, F, 0, nullptr, nullptr, nullptr);
    k_gemv_att<<<NN / 8, 256>>>(att);
    k_seg_softmax<<<NN / 8, 256>>>(ei);
    k_scatter_e<<<NN, 192>>>(ei);
    k_scatter_n<<<NN, 192>>>(ei, hb);
}

extern "C" void kernel_launch(void* const* d_in, const int* in_sizes, int n_in,
                              void* d_out, int out_size) {
    const float* x       = (const float*)d_in[0];
    const int*   ei      = (const int*)  d_in[1];
    const float* eattr   = (const float*)d_in[2];
    const float* gn1_w   = (const float*)d_in[3];
    const float* gn1_b   = (const float*)d_in[4];
    const float* gn1_ms  = (const float*)d_in[5];
    const float* gn2_w   = (const float*)d_in[6];
    const float* gn2_b   = (const float*)d_in[7];
    const float* gn2_ms  = (const float*)d_in[8];
    const float* hg1_W   = (const float*)d_in[9];
    const float* hg1_att = (const float*)d_in[10];
    const float* hg1_b   = (const float*)d_in[11];
    const float* hg2_W   = (const float*)d_in[12];
    const float* hg2_att = (const float*)d_in[13];
    const float* hg2_b   = (const float*)d_in[14];
    const float* fc1_W   = (const float*)d_in[15];
    const float* fc1_b   = (const float*)d_in[16];
    const float* fc2_W   = (const float*)d_in[17];
    const float* fc2_b   = (const float*)d_in[18];
    const float* attn_W1 = (const float*)d_in[19];
    const float* attn_b1 = (const float*)d_in[20];
    const float* attn_W2 = (const float*)d_in[21];
    const float* attn_b2 = (const float*)d_in[22];
    const float* cls_W   = (const float*)d_in[23];
    const float* cls_b   = (const float*)d_in[24];
    const float* center  = (const float*)d_in[25];
    float*       out     = (float*)d_out;

    cudaFuncSetAttribute(k_gemm<256>, cudaFuncAttributeMaxDynamicSharedMemorySize, SMEM256);
    cudaFuncSetAttribute(k_gemm<128>, cudaFuncAttributeMaxDynamicSharedMemorySize, SMEM128);

    float *p_xn, *p_xt, *p_et, *p_eat, *p_h, *p_out1, *p_out2, *p_catT, *p_score;
    float *p_w1t, *p_wt, *p_fwt, *p_colsum, *p_colsq;
    cudaGetSymbolAddress((void**)&p_xn,     g_xn);
    cudaGetSymbolAddress((void**)&p_xt,     g_xt);
    cudaGetSymbolAddress((void**)&p_et,     g_et);
    cudaGetSymbolAddress((void**)&p_eat,    g_eat);
    cudaGetSymbolAddress((void**)&p_h,      g_h);
    cudaGetSymbolAddress((void**)&p_out1,   g_out1);
    cudaGetSymbolAddress((void**)&p_out2,   g_out2);
    cudaGetSymbolAddress((void**)&p_catT,   g_catT);
    cudaGetSymbolAddress((void**)&p_score,  g_score);
    cudaGetSymbolAddress((void**)&p_w1t,    g_w1t);
    cudaGetSymbolAddress((void**)&p_wt,     g_wt);
    cudaGetSymbolAddress((void**)&p_fwt,    g_fwt);
    cudaGetSymbolAddress((void**)&p_colsum, g_colsum);
    cudaGetSymbolAddress((void**)&p_colsq,  g_colsq);

    int *p_offc, *p_offr;
    cudaGetSymbolAddress((void**)&p_offc, g_off_c);
    cudaGetSymbolAddress((void**)&p_offr, g_off_r);
    int *p_cntc, *p_cntr;
    cudaGetSymbolAddress((void**)&p_cntc, g_cnt_c);
    cudaGetSymbolAddress((void**)&p_cntr, g_cnt_r);

    // ---- CSR build (once) + one-time tf32 conversions ----
    k_csr_zero<<<NN / 256, 256>>>();
    k_csr_count<<<NNZ / 256, 256>>>(ei);
    k_scan<<<1, 1024>>>(p_cntc, p_offc);
    k_scan<<<1, 1024>>>(p_cntr, p_offr);
    k_csr_place<<<NNZ / 256, 256>>>(ei);
    k_cvt4<<<(NN * F / 4 + 255) / 256, 256>>>((const float4*)eattr, (float4*)p_eat, NN * F / 4);
    k_cvt4<<<(int)((size_t)NN * NN / 4 / 256), 256>>>((const float4*)attn_W1, (float4*)p_w1t,
                                                      (int)((size_t)NN * NN / 4));

    // ---- conv1 + fc1 ----
    run_conv(x, ei, gn1_w, gn1_b, gn1_ms, hg1_W, hg1_att, hg1_b,
             p_xn, p_xt, p_et, p_eat, p_wt, p_colsum, p_colsq);
    k_cvt4<<<(HIDD * F / 4 + 255) / 256, 256>>>((const float4*)fc1_W, (float4*)p_fwt, HIDD * F / 4);
    k_gemm<128><<<dim3(HIDD / 128, NN / 128), 256, SMEM128>>>(
        p_h, p_fwt, p_out1, HIDD, F, 1, fc1_b, nullptr, nullptr);

    // ---- conv2 (graphnorm reads g_h = h1 before scatter_n overwrites it) + fc2 ----
    run_conv(p_h, ei, gn2_w, gn2_b, gn2_ms, hg2_W, hg2_att, hg2_b,
             p_xn, p_xt, p_et, p_eat, p_wt, p_colsum, p_colsq);
    k_cvt4<<<(HIDD * F / 4 + 255) / 256, 256>>>((const float4*)fc2_W, (float4*)p_fwt, HIDD * F / 4);
    k_gemm<128><<<dim3(HIDD / 128, NN / 128), 256, SMEM128>>>(
        p_h, p_fwt, p_out2, HIDD, F, 1, fc2_b, nullptr, nullptr);

    // ---- catT = [x; out1; out2]^T (tf32 bits, node-contiguous) ----
    k_transpose<<<dim3(F / 32,    NN / 32), dim3(32, 8)>>>(x,      F,    p_catT);
    k_transpose<<<dim3(HIDD / 32, NN / 32), dim3(32, 8)>>>(p_out1, HIDD, p_catT + (size_t)F * NN);
    k_transpose<<<dim3(HIDD / 32, NN / 32), dim3(32, 8)>>>(p_out2, HIDD, p_catT + (size_t)(F + HIDD) * NN);

    // ---- attention: score[d] = sum_j relu(catT@W1^T + b1)[d,j] * W2[j] (fused epilogue) ----
    k_zero_score<<<(DCAT + 255) / 256, 256>>>();
    k_gemm<256><<<dim3(NN / 256, DCAT / 128), 256, SMEM256>>>(
        p_catT, p_w1t, nullptr, NN, NN, 2, attn_b1, attn_W2, p_score);
    k_score_final<<<(DCAT + 255) / 256, 256>>>(attn_b2, center);

    // ---- classifier with score folded into weights ----
    k_wp<<<(OUTD * DCAT + 255) / 256, 256>>>(cls_W);
    k_logits<<<NN * 32 / 256, 256>>>(x, cls_b, out);
}

// round 8
// speedup vs baseline: 4.0097x; 1.0000x over previous
#include <cuda_runtime.h>
#include <cstdint>

#define NN   8192
#define F    768
#define HIDD 384
#define OUTD 10
#define NNZ  (NN * 16)
#define DCAT (F + 2 * HIDD)

#define KC      32                 // fp32 per K-chunk (128 B per smem row)
#define STAGES  3
#define ABYTES  (128 * 128)        // A tile: 128 rows x 128 B

// ---------------- scratch (device globals; no allocation allowed) ----------------
__device__ float    g_xn[NN * F];
__device__ float    g_xt[NN * F];
__device__ float    g_et[NN * F];
__device__ float    g_eat[NN * F];      // eattr pre-converted to tf32 bits
__device__ float    g_efeat[NN * F];
__device__ float    g_h[NN * F];
__device__ float    g_out1[NN * HIDD];
__device__ float    g_out2[NN * HIDD];
__device__ float    g_catT[(size_t)DCAT * NN];
__device__ float    g_w1t[(size_t)NN * NN];   // attn_W1 tf32 bits
__device__ float    g_wt[F * F];              // hg W tf32 bits
__device__ float    g_fwt[HIDD * F];          // fc W tf32 bits
__device__ float    g_alpha[NNZ];
__device__ float    g_ax[NN];
__device__ float    g_ae[NN];
__device__ float    g_score[DCAT];
__device__ float    g_wp[OUTD * DCAT];
// CSR structures (built once; edge_index identical for both convs)
__device__ int      g_cnt_c[NN], g_cnt_r[NN];
__device__ int      g_cur_c[NN], g_cur_r[NN];
__device__ int      g_off_c[NN + 1], g_off_r[NN + 1];
__device__ int      g_perm_c[NNZ], g_perm_r[NNZ];

// ---------------- PTX helpers (plain sm_103-safe) ----------------
__device__ __forceinline__ uint32_t smem_u32(const void* p) {
    uint32_t a;
    asm("{ .reg .u64 t; cvta.to.shared.u64 t, %1; cvt.u32.u64 %0, t; }" : "=r"(a) : "l"(p));
    return a;
}
#define CP_ASYNC16(d, s) \
    asm volatile("cp.async.cg.shared.global [%0], [%1], 16;" :: "r"(d), "l"(s) : "memory")
#define CP_COMMIT()      asm volatile("cp.async.commit_group;" ::: "memory")
#define CP_WAIT(n)       asm volatile("cp.async.wait_group %0;" :: "n"(n) : "memory")

__device__ __forceinline__ uint32_t f2tf(float f) {
    uint32_t u;
    asm("cvt.rna.tf32.f32 %0, %1;" : "=r"(u) : "f"(f));
    return u;
}
__device__ __forceinline__ float round_tf(float f) { return __uint_as_float(f2tf(f)); }

__device__ __forceinline__ void mma_tf32(float* c, const uint32_t* a, const uint32_t* b) {
    asm volatile(
        "mma.sync.aligned.m16n8k8.row.col.f32.tf32.tf32.f32 "
        "{%0,%1,%2,%3}, {%4,%5,%6,%7}, {%8,%9}, {%0,%1,%2,%3};"
        : "+f"(c[0]), "+f"(c[1]), "+f"(c[2]), "+f"(c[3])
        : "r"(a[0]), "r"(a[1]), "r"(a[2]), "r"(a[3]), "r"(b[0]), "r"(b[1]));
}

// ---------------- tf32 mma.sync NT GEMM: C[M,Nc] = A[M,K] * B[Nc,K]^T ----------------
// Inputs are PRE-ROUNDED tf32 bit patterns (no cvt in hot loop).
// CTA tile 128 x NT, 8 warps (2M x 4N), warp tile 64 x (NT/4). K-chunk 32 fp32.
// mode 0: store C. mode 1: C = lrelu(acc + bias[col], 0.01).
// mode 2: no C; score[row] += sum_col relu(acc + bias[col]) * w2[col].
template <int NT>
__global__ void __launch_bounds__(256, 1) k_gemm(
    const float* __restrict__ A, const float* __restrict__ B, float* __restrict__ C,
    int Nc, int K, int mode,
    const float* __restrict__ bias, const float* __restrict__ w2,
    float* __restrict__ score)
{
    constexpr int N8     = NT / 32;            // n8 tiles per warp (8 or 4)
    constexpr int BBYTES = NT * 128;
    constexpr int STB    = ABYTES + BBYTES;
    extern __shared__ char dsmem[];
    __shared__ float red[128];

    const int tid  = threadIdx.x;
    const int warp = tid >> 5;
    const int lane = tid & 31;
    const int qid  = lane >> 2;
    const int kid  = lane & 3;
    const int wm   = (warp >> 2) * 64;
    const int wn   = (warp & 3) * (NT / 4);
    const int row0 = blockIdx.y * 128;
    const int col0 = blockIdx.x * NT;
    const int nch  = K / KC;
    const uint32_t sw = (uint32_t)qid * 16;
    const uint32_t sm0   = smem_u32(dsmem);
    const uint32_t data0 = (sm0 + 1023u) & ~1023u;

    float c[4][N8][4];
#pragma unroll
    for (int i = 0; i < 4; i++)
#pragma unroll
        for (int j = 0; j < N8; j++)
#pragma unroll
            for (int k = 0; k < 4; k++) c[i][j][k] = 0.f;

    auto load_chunk = [&](int ch, int s) {
        const int k0 = ch * KC;
        const uint32_t sa = data0 + (uint32_t)s * STB;
        const uint32_t sb = sa + ABYTES;
        const float* Ag = A + (size_t)row0 * K + k0;
        const float* Bg = B + (size_t)col0 * K + k0;
#pragma unroll
        for (int w = 0; w < 4; w++) {
            int idx = tid + w * 256;
            int r = idx >> 3, c4 = idx & 7;
            uint32_t off = (uint32_t)r * 128 + (((uint32_t)c4 * 16) ^ (((uint32_t)r & 7) * 16));
            CP_ASYNC16(sa + off, Ag + (size_t)r * K + c4 * 4);
        }
#pragma unroll
        for (int w = 0; w < NT / 32; w++) {
            int idx = tid + w * 256;
            int r = idx >> 3, c4 = idx & 7;
            uint32_t off = (uint32_t)r * 128 + (((uint32_t)c4 * 16) ^ (((uint32_t)r & 7) * 16));
            CP_ASYNC16(sb + off, Bg + (size_t)r * K + c4 * 4);
        }
        CP_COMMIT();
    };

    for (int i = 0; i < STAGES; i++) load_chunk(i, i);

    for (int i = 0; i < nch; i++) {
        const int s = i % STAGES;
        CP_WAIT(STAGES - 1);
        __syncthreads();

        const char* sA = dsmem + ((data0 - sm0) + (uint32_t)s * STB);
        const char* sB = sA + ABYTES;
#pragma unroll
        for (int k8 = 0; k8 < 4; k8++) {
            const uint32_t x0   = (uint32_t)(k8 * 32 + kid * 4);
            const uint32_t off0 = x0 ^ sw;
            const uint32_t off1 = (x0 + 16) ^ sw;
            uint32_t a[4][4], b[N8][2];
#pragma unroll
            for (int mt = 0; mt < 4; mt++) {
                const char* p = sA + (size_t)(wm + mt * 16 + qid) * 128;
                a[mt][0] = *(const uint32_t*)(p + off0);
                a[mt][1] = *(const uint32_t*)(p + 1024 + off0);
                a[mt][2] = *(const uint32_t*)(p + off1);
                a[mt][3] = *(const uint32_t*)(p + 1024 + off1);
            }
#pragma unroll
            for (int nt = 0; nt < N8; nt++) {
                const char* p = sB + (size_t)(wn + nt * 8 + qid) * 128;
                b[nt][0] = *(const uint32_t*)(p + off0);
                b[nt][1] = *(const uint32_t*)(p + off1);
            }
#pragma unroll
            for (int mt = 0; mt < 4; mt++)
#pragma unroll
                for (int nt = 0; nt < N8; nt++)
                    mma_tf32(c[mt][nt], a[mt], b[nt]);
        }
        __syncthreads();
        if (i + STAGES < nch) load_chunk(i + STAGES, s);
        else                  CP_COMMIT();
    }

    // ---------------- epilogue ----------------
    if (mode == 2) {
        float bv[N8 * 2], wv[N8 * 2];
#pragma unroll
        for (int nt = 0; nt < N8; nt++)
#pragma unroll
            for (int j = 0; j < 2; j++) {
                int col = col0 + wn + nt * 8 + kid * 2 + j;
                bv[nt * 2 + j] = bias[col];
                wv[nt * 2 + j] = w2[col];
            }
        if (tid < 128) red[tid] = 0.f;
        __syncthreads();
#pragma unroll
        for (int mt = 0; mt < 4; mt++)
#pragma unroll
            for (int h = 0; h < 2; h++) {
                float part = 0.f;
#pragma unroll
                for (int nt = 0; nt < N8; nt++)
#pragma unroll
                    for (int j = 0; j < 2; j++) {
                        float v = c[mt][nt][h * 2 + j] + bv[nt * 2 + j];
                        part = fmaf(fmaxf(v, 0.f), wv[nt * 2 + j], part);
                    }
                part += __shfl_xor_sync(0xffffffffu, part, 1);
                part += __shfl_xor_sync(0xffffffffu, part, 2);
                if (kid == 0)
                    atomicAdd(&red[wm + mt * 16 + qid + h * 8], part);
            }
        __syncthreads();
        if (tid < 128) atomicAdd(&score[row0 + tid], red[tid]);
        return;
    }

#pragma unroll
    for (int mt = 0; mt < 4; mt++)
#pragma unroll
        for (int h = 0; h < 2; h++) {
            int row = row0 + wm + mt * 16 + qid + h * 8;
            float* Cp = C + (size_t)row * Nc + col0 + wn;
#pragma unroll
            for (int nt = 0; nt < N8; nt++) {
                float v0 = c[mt][nt][h * 2 + 0];
                float v1 = c[mt][nt][h * 2 + 1];
                int coll = wn + nt * 8 + kid * 2;
                if (mode == 1) {
                    v0 += bias[col0 + coll];
                    v1 += bias[col0 + coll + 1];
                    v0 = v0 >= 0.f ? v0 : 0.01f * v0;
                    v1 = v1 >= 0.f ? v1 : 0.01f * v1;
                }
                *(float2*)(Cp + nt * 8 + kid * 2) = make_float2(v0, v1);
            }
        }
}

// ---------------- tf32 pre-conversion ----------------
__global__ void k_cvt4(const float4* __restrict__ src, float4* __restrict__ dst, int n4) {
    int i = blockIdx.x * blockDim.x + threadIdx.x;
    if (i >= n4) return;
    float4 v = src[i];
    v.x = round_tf(v.x); v.y = round_tf(v.y); v.z = round_tf(v.z); v.w = round_tf(v.w);
    dst[i] = v;
}

// ---------------- CSR build (once; edge_index shared by both convs) ----------------
__global__ void k_csr_zero() {
    int i = blockIdx.x * blockDim.x + threadIdx.x;
    if (i < NN) { g_cnt_c[i] = 0; g_cnt_r[i] = 0; g_cur_c[i] = 0; g_cur_r[i] = 0; }
}
__global__ void k_csr_count(const int* __restrict__ ei) {
    int e = blockIdx.x * blockDim.x + threadIdx.x;
    if (e >= NNZ) return;
    atomicAdd(&g_cnt_c[ei[NNZ + e]], 1);
    atomicAdd(&g_cnt_r[ei[e]], 1);
}
// exclusive scan of 8192 ints, single block of 1024 threads
__global__ void k_scan(const int* __restrict__ cnt, int* __restrict__ off) {
    __shared__ int part[1024];
    int t = threadIdx.x;
    int loc[8];
    int s = 0;
#pragma unroll
    for (int i = 0; i < 8; i++) { loc[i] = s; s += cnt[t * 8 + i]; }
    part[t] = s;
    __syncthreads();
    for (int d = 1; d < 1024; d <<= 1) {
        int v = (t >= d) ? part[t - d] : 0;
        __syncthreads();
        part[t] += v;
        __syncthreads();
    }
    int base = (t == 0) ? 0 : part[t - 1];
#pragma unroll
    for (int i = 0; i < 8; i++) off[t * 8 + i] = base + loc[i];
    if (t == 1023) off[NN] = part[1023];
}
__global__ void k_csr_place(const int* __restrict__ ei) {
    int e = blockIdx.x * blockDim.x + threadIdx.x;
    if (e >= NNZ) return;
    int r = ei[e], c = ei[NNZ + e];
    int pc = atomicAdd(&g_cur_c[c], 1);
    g_perm_c[g_off_c[c] + pc] = e;
    int pr = atomicAdd(&g_cur_r[r], 1);
    g_perm_r[g_off_r[r] + pr] = e;
}

// ---------------- small utility kernels ----------------
__global__ void k_zero_gn(float* __restrict__ colsum, float* __restrict__ colsq) {
    int c = threadIdx.x;
    if (c < F) { colsum[c] = 0.f; colsq[c] = 0.f; }
}
__device__ float g_colsum[F];
__device__ float g_colsq[F];

__global__ void k_zero_score() {
    int d = blockIdx.x * blockDim.x + threadIdx.x;
    if (d < DCAT) g_score[d] = 0.f;
}

// ---------------- GraphNorm ----------------
__global__ void k_gn_reduce(const float* __restrict__ X) {
    int c  = threadIdx.x;
    int r0 = blockIdx.x * 64;
    float s = 0.f, q = 0.f;
    for (int i = 0; i < 64; i++) {
        float v = X[(size_t)(r0 + i) * F + c];
        s += v;
        q += v * v;
    }
    atomicAdd(&g_colsum[c], s);
    atomicAdd(&g_colsq[c], q);
}

__global__ void k_gn_apply(const float* __restrict__ X,
                           const float* __restrict__ w,
                           const float* __restrict__ b,
                           const float* __restrict__ ms) {
    int idx = blockIdx.x * blockDim.x + threadIdx.x;
    if (idx >= NN * F) return;
    int c = idx % F;
    float invN  = 1.f / (float)NN;
    float mean  = g_colsum[c] * invN;
    float m     = ms[c];
    float var   = g_colsq[c] * invN - m * (2.f - m) * mean * mean;
    float outv  = X[idx] - m * mean;
    g_xn[idx]   = round_tf(w[c] * outv * rsqrtf(var + 1e-5f) + b[c]);  // tf32: GEMM input
}

// ---------------- attention-coefficient GEMVs ----------------
__global__ void k_gemv_att(const float* __restrict__ att) {
    int w    = (blockIdx.x * blockDim.x + threadIdx.x) >> 5;
    int lane = threadIdx.x & 31;
    if (w >= NN) return;
    const float* xr = g_xt + (size_t)w * F;
    const float* er = g_et + (size_t)w * F;
    float s1 = 0.f, s2 = 0.f;
    for (int i = lane; i < F; i += 32) {
        s1 = fmaf(xr[i], att[i],     s1);
        s2 = fmaf(er[i], att[F + i], s2);
    }
#pragma unroll
    for (int off = 16; off; off >>= 1) {
        s1 += __shfl_xor_sync(0xffffffffu, s1, off);
        s2 += __shfl_xor_sync(0xffffffffu, s2, off);
    }
    if (lane == 0) { g_ax[w] = s1; g_ae[w] = s2; }
}

// ---------------- fused per-hyperedge softmax (warp per segment, no atomics) ----------------
__global__ void k_seg_softmax(const int* __restrict__ ei) {
    int w    = (blockIdx.x * blockDim.x + threadIdx.x) >> 5;
    int lane = threadIdx.x & 31;
    if (w >= NN) return;
    int s = g_off_c[w], n = g_off_c[w + 1] - s;
    if (n == 0) return;
    float aec = g_ae[w];
    float m = -3.4e38f;
    for (int i = lane; i < n; i += 32) {
        int e = g_perm_c[s + i];
        float a = g_ax[ei[e]] + aec;
        a = a >= 0.f ? a : 0.2f * a;
        g_alpha[e] = a;
        m = fmaxf(m, a);
    }
#pragma unroll
    for (int o = 16; o; o >>= 1) m = fmaxf(m, __shfl_xor_sync(0xffffffffu, m, o));
    float sum = 0.f;
    for (int i = lane; i < n; i += 32) {
        int e = g_perm_c[s + i];
        float ex = expf(g_alpha[e] - m);
        g_alpha[e] = ex;
        sum += ex;
    }
#pragma unroll
    for (int o = 16; o; o >>= 1) sum += __shfl_xor_sync(0xffffffffu, sum, o);
    float inv = 1.f / (sum + 1e-16f);
    for (int i = lane; i < n; i += 32) g_alpha[g_perm_c[s + i]] *= inv;
}

// ---------------- atomic-free scatters: block per segment, register accumulation ----------------
#define SCH 64
__global__ void k_scatter_e(const int* __restrict__ ei) {   // node -> hyperedge
    __shared__ float scoef[SCH];
    __shared__ int   sidx[SCH];
    int c = blockIdx.x;
    int s = g_off_c[c], end = g_off_c[c + 1];
    int n = end - s;
    float bn = n > 0 ? 1.f / (float)n : 0.f;
    int f = threadIdx.x * 4;
    float4 acc = make_float4(0.f, 0.f, 0.f, 0.f);
    while (s < end) {
        int chunk = min(SCH, end - s);
        __syncthreads();
        if ((int)threadIdx.x < chunk) {
            int e = g_perm_c[s + threadIdx.x];
            scoef[threadIdx.x] = bn * g_alpha[e];
            sidx[threadIdx.x]  = ei[e];                 // row
        }
        __syncthreads();
        for (int j = 0; j < chunk; j++) {
            float cf = scoef[j];
            float4 v = *(const float4*)&g_xt[(size_t)sidx[j] * F + f];
            acc.x = fmaf(cf, v.x, acc.x);
            acc.y = fmaf(cf, v.y, acc.y);
            acc.z = fmaf(cf, v.z, acc.z);
            acc.w = fmaf(cf, v.w, acc.w);
        }
        s += chunk;
    }
    *(float4*)&g_efeat[(size_t)c * F + f] = acc;
}

__global__ void k_scatter_n(const int* __restrict__ ei, const float* __restrict__ bias) {
    __shared__ float scoef[SCH];
    __shared__ int   sidx[SCH];
    int r = blockIdx.x;
    int s = g_off_r[r], end = g_off_r[r + 1];
    int n = end - s;
    float dn = n > 0 ? 1.f / (float)n : 0.f;
    int f = threadIdx.x * 4;
    float4 acc = make_float4(0.f, 0.f, 0.f, 0.f);
    while (s < end) {
        int chunk = min(SCH, end - s);
        __syncthreads();
        if ((int)threadIdx.x < chunk) {
            int e = g_perm_r[s + threadIdx.x];
            scoef[threadIdx.x] = dn * g_alpha[e];
            sidx[threadIdx.x]  = ei[NNZ + e];           // col
        }
        __syncthreads();
        for (int j = 0; j < chunk; j++) {
            float cf = scoef[j];
            float4 v = *(const float4*)&g_efeat[(size_t)sidx[j] * F + f];
            acc.x = fmaf(cf, v.x, acc.x);
            acc.y = fmaf(cf, v.y, acc.y);
            acc.z = fmaf(cf, v.z, acc.z);
            acc.w = fmaf(cf, v.w, acc.w);
        }
        s += chunk;
    }
    // fused: + bias, leaky relu 0.01, tf32 round (h feeds only GEMMs / GN / stats)
    float4 b4 = *(const float4*)&bias[f];
    acc.x += b4.x; acc.y += b4.y; acc.z += b4.z; acc.w += b4.w;
    acc.x = acc.x >= 0.f ? acc.x : 0.01f * acc.x;
    acc.y = acc.y >= 0.f ? acc.y : 0.01f * acc.y;
    acc.z = acc.z >= 0.f ? acc.z : 0.01f * acc.z;
    acc.w = acc.w >= 0.f ? acc.w : 0.01f * acc.w;
    acc.x = round_tf(acc.x); acc.y = round_tf(acc.y);
    acc.z = round_tf(acc.z); acc.w = round_tf(acc.w);
    *(float4*)&g_h[(size_t)r * F + f] = acc;
}

// ---------------- transpose src[NN,C] -> dst[c*NN + r], tf32-rounded (GEMM input) ----------------
__global__ void k_transpose(const float* __restrict__ src, int C, float* __restrict__ dst) {
    __shared__ float t[32][33];
    int c0 = blockIdx.x * 32, r0 = blockIdx.y * 32;
    int tx = threadIdx.x, ty = threadIdx.y;
#pragma unroll
    for (int i = 0; i < 4; i++)
        t[ty + 8 * i][tx] = src[(size_t)(r0 + ty + 8 * i) * C + c0 + tx];
    __syncthreads();
#pragma unroll
    for (int i = 0; i < 4; i++)
        dst[(size_t)(c0 + ty + 8 * i) * NN + r0 + tx] = round_tf(t[tx][ty + 8 * i]);
}

// ---------------- score finalize + folded classifier ----------------
__global__ void k_score_final(const float* __restrict__ b2, const float* __restrict__ center) {
    int d = blockIdx.x * blockDim.x + threadIdx.x;
    if (d >= DCAT) return;
    float r = g_score[d] + b2[0];
    float sg = 1.f / (1.f + expf(-r));
    g_score[d] = sg - center[d];
}

__global__ void k_wp(const float* __restrict__ clsW) {
    int idx = blockIdx.x * blockDim.x + threadIdx.x;
    if (idx >= OUTD * DCAT) return;
    g_wp[idx] = clsW[idx] * g_score[idx % DCAT];
}

__global__ void k_logits(const float* __restrict__ x, const float* __restrict__ clsb,
                         float* __restrict__ out) {
    int n    = (blockIdx.x * blockDim.x + threadIdx.x) >> 5;
    int lane = threadIdx.x & 31;
    if (n >= NN) return;
    float acc[OUTD];
#pragma unroll
    for (int o = 0; o < OUTD; o++) acc[o] = 0.f;

    const float* xr = x + (size_t)n * F;
#pragma unroll
    for (int it = 0; it < 6; it++) {
        int i = lane * 4 + it * 128;
        float4 v = *(const float4*)&xr[i];
#pragma unroll
        for (int o = 0; o < OUTD; o++) {
            float4 w = *(const float4*)&g_wp[o * DCAT + i];
            acc[o] += v.x * w.x + v.y * w.y + v.z * w.z + v.w * w.w;
        }
    }
    const float* o1 = g_out1 + (size_t)n * HIDD;
#pragma unroll
    for (int it = 0; it < 3; it++) {
        int i = lane * 4 + it * 128;
        float4 v = *(const float4*)&o1[i];
#pragma unroll
        for (int o = 0; o < OUTD; o++) {
            float4 w = *(const float4*)&g_wp[o * DCAT + F + i];
            acc[o] += v.x * w.x + v.y * w.y + v.z * w.z + v.w * w.w;
        }
    }
    const float* o2 = g_out2 + (size_t)n * HIDD;
#pragma unroll
    for (int it = 0; it < 3; it++) {
        int i = lane * 4 + it * 128;
        float4 v = *(const float4*)&o2[i];
#pragma unroll
        for (int o = 0; o < OUTD; o++) {
            float4 w = *(const float4*)&g_wp[o * DCAT + F + HIDD + i];
            acc[o] += v.x * w.x + v.y * w.y + v.z * w.z + v.w * w.w;
        }
    }
#pragma unroll
    for (int o = 0; o < OUTD; o++) {
        float v = acc[o];
#pragma unroll
        for (int off = 16; off; off >>= 1) v += __shfl_xor_sync(0xffffffffu, v, off);
        if (lane == 0) out[(size_t)n * OUTD + o] = v + clsb[o];
    }
}

// ---------------- host-side driver ----------------
static const int SMEM256 = STAGES * (ABYTES + 256 * 128) + 1024;  // 148480
static const int SMEM128 = STAGES * (ABYTES + 128 * 128) + 1024;  //  99328

static void run_conv(const float* feat_in, const int* ei,
                     const float* gw, const float* gb, const float* gms,
                     const float* W, const float* att, const float* hb,
                     float* p_xn, float* p_xt, float* p_et, float* p_eat,
                     float* p_wt, float* p_colsum, float* p_colsq)
{
    k_zero_gn<<<1, 768>>>(p_colsum, p_colsq);
    k_gn_reduce<<<NN / 64, 768>>>(feat_in);
    k_gn_apply<<<NN * F / 256, 256>>>(feat_in, gw, gb, gms);
    k_cvt4<<<(F * F / 4 + 255) / 256, 256>>>((const float4*)W, (float4*)p_wt, F * F / 4);
    k_gemm<256><<<dim3(F / 256, NN / 128), 256, SMEM256>>>(
        p_xn, p_wt, p_xt, F, F, 0, nullptr, nullptr, nullptr);
    k_gemm<256><<<dim3(F / 256, NN / 128), 256, SMEM256>>>(
        p_eat, p_wt, p_et, F, F, 0, nullptr, nullptr, nullptr);
    k_gemv_att<<<NN / 8, 256>>>(att);
    k_seg_softmax<<<NN / 8, 256>>>(ei);
    k_scatter_e<<<NN, 192>>>(ei);
    k_scatter_n<<<NN, 192>>>(ei, hb);
}

extern "C" void kernel_launch(void* const* d_in, const int* in_sizes, int n_in,
                              void* d_out, int out_size) {
    const float* x       = (const float*)d_in[0];
    const int*   ei      = (const int*)  d_in[1];
    const float* eattr   = (const float*)d_in[2];
    const float* gn1_w   = (const float*)d_in[3];
    const float* gn1_b   = (const float*)d_in[4];
    const float* gn1_ms  = (const float*)d_in[5];
    const float* gn2_w   = (const float*)d_in[6];
    const float* gn2_b   = (const float*)d_in[7];
    const float* gn2_ms  = (const float*)d_in[8];
    const float* hg1_W   = (const float*)d_in[9];
    const float* hg1_att = (const float*)d_in[10];
    const float* hg1_b   = (const float*)d_in[11];
    const float* hg2_W   = (const float*)d_in[12];
    const float* hg2_att = (const float*)d_in[13];
    const float* hg2_b   = (const float*)d_in[14];
    const float* fc1_W   = (const float*)d_in[15];
    const float* fc1_b   = (const float*)d_in[16];
    const float* fc2_W   = (const float*)d_in[17];
    const float* fc2_b   = (const float*)d_in[18];
    const float* attn_W1 = (const float*)d_in[19];
    const float* attn_b1 = (const float*)d_in[20];
    const float* attn_W2 = (const float*)d_in[21];
    const float* attn_b2 = (const float*)d_in[22];
    const float* cls_W   = (const float*)d_in[23];
    const float* cls_b   = (const float*)d_in[24];
    const float* center  = (const float*)d_in[25];
    float*       out     = (float*)d_out;

    cudaFuncSetAttribute(k_gemm<256>, cudaFuncAttributeMaxDynamicSharedMemorySize, SMEM256);
    cudaFuncSetAttribute(k_gemm<128>, cudaFuncAttributeMaxDynamicSharedMemorySize, SMEM128);

    float *p_xn, *p_xt, *p_et, *p_eat, *p_h, *p_out1, *p_out2, *p_catT, *p_score;
    float *p_w1t, *p_wt, *p_fwt, *p_colsum, *p_colsq;
    cudaGetSymbolAddress((void**)&p_xn,     g_xn);
    cudaGetSymbolAddress((void**)&p_xt,     g_xt);
    cudaGetSymbolAddress((void**)&p_et,     g_et);
    cudaGetSymbolAddress((void**)&p_eat,    g_eat);
    cudaGetSymbolAddress((void**)&p_h,      g_h);
    cudaGetSymbolAddress((void**)&p_out1,   g_out1);
    cudaGetSymbolAddress((void**)&p_out2,   g_out2);
    cudaGetSymbolAddress((void**)&p_catT,   g_catT);
    cudaGetSymbolAddress((void**)&p_score,  g_score);
    cudaGetSymbolAddress((void**)&p_w1t,    g_w1t);
    cudaGetSymbolAddress((void**)&p_wt,     g_wt);
    cudaGetSymbolAddress((void**)&p_fwt,    g_fwt);
    cudaGetSymbolAddress((void**)&p_colsum, g_colsum);
    cudaGetSymbolAddress((void**)&p_colsq,  g_colsq);

    int *p_offc, *p_offr;
    cudaGetSymbolAddress((void**)&p_offc, g_off_c);
    cudaGetSymbolAddress((void**)&p_offr, g_off_r);
    int *p_cntc, *p_cntr;
    cudaGetSymbolAddress((void**)&p_cntc, g_cnt_c);
    cudaGetSymbolAddress((void**)&p_cntr, g_cnt_r);

    // ---- CSR build (once) + one-time tf32 conversions ----
    k_csr_zero<<<NN / 256, 256>>>();
    k_csr_count<<<NNZ / 256, 256>>>(ei);
    k_scan<<<1, 1024>>>(p_cntc, p_offc);
    k_scan<<<1, 1024>>>(p_cntr, p_offr);
    k_csr_place<<<NNZ / 256, 256>>>(ei);
    k_cvt4<<<(NN * F / 4 + 255) / 256, 256>>>((const float4*)eattr, (float4*)p_eat, NN * F / 4);
    k_cvt4<<<(int)((size_t)NN * NN / 4 / 256), 256>>>((const float4*)attn_W1, (float4*)p_w1t,
                                                      (int)((size_t)NN * NN / 4));

    // ---- conv1 + fc1 ----
    run_conv(x, ei, gn1_w, gn1_b, gn1_ms, hg1_W, hg1_att, hg1_b,
             p_xn, p_xt, p_et, p_eat, p_wt, p_colsum, p_colsq);
    k_cvt4<<<(HIDD * F / 4 + 255) / 256, 256>>>((const float4*)fc1_W, (float4*)p_fwt, HIDD * F / 4);
    k_gemm<128><<<dim3(HIDD / 128, NN / 128), 256, SMEM128>>>(
        p_h, p_fwt, p_out1, HIDD, F, 1, fc1_b, nullptr, nullptr);

    // ---- conv2 (graphnorm reads g_h = h1 before scatter_n overwrites it) + fc2 ----
    run_conv(p_h, ei, gn2_w, gn2_b, gn2_ms, hg2_W, hg2_att, hg2_b,
             p_xn, p_xt, p_et, p_eat, p_wt, p_colsum, p_colsq);
    k_cvt4<<<(HIDD * F / 4 + 255) / 256, 256>>>((const float4*)fc2_W, (float4*)p_fwt, HIDD * F / 4);
    k_gemm<128><<<dim3(HIDD / 128, NN / 128), 256, SMEM128>>>(
        p_h, p_fwt, p_out2, HIDD, F, 1, fc2_b, nullptr, nullptr);

    // ---- catT = [x; out1; out2]^T (tf32 bits, node-contiguous) ----
    k_transpose<<<dim3(F / 32,    NN / 32), dim3(32, 8)>>>(x,      F,    p_catT);
    k_transpose<<<dim3(HIDD / 32, NN / 32), dim3(32, 8)>>>(p_out1, HIDD, p_catT + (size_t)F * NN);
    k_transpose<<<dim3(HIDD / 32, NN / 32), dim3(32, 8)>>>(p_out2, HIDD, p_catT + (size_t)(F + HIDD) * NN);

    // ---- attention: score[d] = sum_j relu(catT@W1^T + b1)[d,j] * W2[j] (fused epilogue) ----
    k_zero_score<<<(DCAT + 255) / 256, 256>>>();
    k_gemm<256><<<dim3(NN / 256, DCAT / 128), 256, SMEM256>>>(
        p_catT, p_w1t, nullptr, NN, NN, 2, attn_b1, attn_W2, p_score);
    k_score_final<<<(DCAT + 255) / 256, 256>>>(attn_b2, center);

    // ---- classifier with score folded into weights ----
    k_wp<<<(OUTD * DCAT + 255) / 256, 256>>>(cls_W);
    k_logits<<<NN * 32 / 256, 256>>>(x, cls_b, out);
}